// round 10
// baseline (speedup 1.0000x reference)
#include <cuda_runtime.h>
#include <cuda_bf16.h>
#include <cstdint>

#define NR 65536
typedef __nv_bfloat16 bf16;

// ----------------------------- device scratch ------------------------------
__device__ float g_u[(size_t)NR * 1024];
__device__ bf16  g_cHi[(size_t)NR * 192];   // concat(z,f) padded to K=192, hi
__device__ bf16  g_cLo[(size_t)NR * 192];
__device__ bf16  g_uHi[(size_t)NR * 1024];
__device__ bf16  g_uLo[(size_t)NR * 1024];
__device__ bf16  g_hiA[(size_t)NR * 512];
__device__ bf16  g_loA[(size_t)NR * 512];
__device__ bf16  g_hiB[(size_t)NR * 512];
__device__ bf16  g_loB[(size_t)NR * 512];
__device__ float g_v[(size_t)NR * 256];
__device__ float g_x[NR];
__device__ bf16  g_WhhHi[1536 * 512];
__device__ bf16  g_WhhLo[1536 * 512];
__device__ bf16  g_Wo1Hi[256 * 512];     // transposed [N=256, K=512]
__device__ bf16  g_Wo1Lo[256 * 512];
__device__ bf16  g_W2Hi[512 * 1024];     // transposed [N=512, K=1024]
__device__ bf16  g_W2Lo[512 * 1024];
__device__ bf16  g_W1Hi[1024 * 192];     // transposed+padded [N=1024, K=192]
__device__ bf16  g_W1Lo[1024 * 192];

// ----------------------------- small helpers -------------------------------
__device__ __forceinline__ float sig_(float x) { return 1.0f / (1.0f + expf(-x)); }
__device__ __forceinline__ float gelu_(float x) {
    return 0.5f * x * (1.0f + erff(x * 0.70710678f));
}
__device__ __forceinline__ uint32_t smem_u32(const void* p) {
    uint32_t a;
    asm("{ .reg .u64 t; cvta.to.shared.u64 t, %1; cvt.u32.u64 %0, t; }" : "=r"(a) : "l"(p));
    return a;
}
__device__ __forceinline__ uint32_t swz(uint32_t off) { return off ^ ((off >> 3) & 0x70); }

__device__ __forceinline__ void cpasync16(uint32_t saddr, const void* gptr) {
    asm volatile("{ .reg .u64 g; cvta.to.global.u64 g, %1; "
                 "cp.async.cg.shared.global [%0], [g], 16; }"
                 :: "r"(saddr), "l"(gptr) : "memory");
}
#define CP_COMMIT() asm volatile("cp.async.commit_group;" ::: "memory")
#define CP_WAIT1()  asm volatile("cp.async.wait_group 1;" ::: "memory")
#define CP_WAIT0()  asm volatile("cp.async.wait_group 0;" ::: "memory")

__device__ __forceinline__ void ldmx4(uint32_t* r, uint32_t addr) {
    asm volatile("ldmatrix.sync.aligned.m8n8.x4.shared.b16 {%0,%1,%2,%3}, [%4];"
        : "=r"(r[0]), "=r"(r[1]), "=r"(r[2]), "=r"(r[3]) : "r"(addr));
}
__device__ __forceinline__ void mma_bf16(float* d, const uint32_t* a, const uint32_t* b) {
    asm volatile("mma.sync.aligned.m16n8k16.row.col.f32.bf16.bf16.f32 "
        "{%0,%1,%2,%3}, {%4,%5,%6,%7}, {%8,%9}, {%0,%1,%2,%3};"
        : "+f"(d[0]), "+f"(d[1]), "+f"(d[2]), "+f"(d[3])
        : "r"(a[0]), "r"(a[1]), "r"(a[2]), "r"(a[3]), "r"(b[0]), "r"(b[1]));
}

// =========================== init-path kernels =============================
// concat(z,f) -> bf16 hi/lo planes, K padded 160 -> 192 with zeros
__global__ void k_prep(const float* __restrict__ z, const float* __restrict__ f) {
    size_t i = (size_t)blockIdx.x * blockDim.x + threadIdx.x;
    if (i >= (size_t)NR * 192) return;
    int row = (int)(i / 192), col = (int)(i % 192);
    float x = (col < 128) ? z[(size_t)row * 128 + col]
            : (col < 160) ? f[(size_t)row * 32 + col - 128] : 0.f;
    bf16 h = __float2bfloat16(x);
    g_cHi[i] = h;
    g_cLo[i] = __float2bfloat16(x - __bfloat162float(h));
}

// u -> gelu(LN(u)), written as bf16 hi/lo planes
__global__ __launch_bounds__(256) void k_lngelu(
    const float* __restrict__ g1, const float* __restrict__ be1)
{
    const size_t row = blockIdx.x;
    const int tid = threadIdx.x, lane = tid & 31, w = tid >> 5;
    const float* up = g_u + row * 1024 + tid * 4;
    float4 v = *(const float4*)up;
    __shared__ float red[8];
    float s = v.x + v.y + v.z + v.w;
#pragma unroll
    for (int m = 16; m >= 1; m >>= 1) s += __shfl_xor_sync(~0u, s, m);
    if (lane == 0) red[w] = s;
    __syncthreads();
    float tot = 0.f;
#pragma unroll
    for (int i = 0; i < 8; ++i) tot += red[i];
    const float mean = tot * (1.0f / 1024.0f);
    float dx = v.x - mean, dy = v.y - mean, dz = v.z - mean, dw = v.w - mean;
    float q = dx * dx + dy * dy + dz * dz + dw * dw;
#pragma unroll
    for (int m = 16; m >= 1; m >>= 1) q += __shfl_xor_sync(~0u, q, m);
    __syncthreads();
    if (lane == 0) red[w] = q;
    __syncthreads();
    float qt = 0.f;
#pragma unroll
    for (int i = 0; i < 8; ++i) qt += red[i];
    const float rstd = rsqrtf(qt * (1.0f / 1024.0f) + 1e-5f);
    const int j = tid * 4;
    float4 g4 = *(const float4*)&g1[j];
    float4 b4 = *(const float4*)&be1[j];
    float o[4];
    o[0] = gelu_(dx * rstd * g4.x + b4.x);
    o[1] = gelu_(dy * rstd * g4.y + b4.y);
    o[2] = gelu_(dz * rstd * g4.z + b4.z);
    o[3] = gelu_(dw * rstd * g4.w + b4.w);
    __align__(8) bf16 hb[4], lb[4];
#pragma unroll
    for (int c = 0; c < 4; ++c) {
        bf16 h = __float2bfloat16(o[c]);
        hb[c] = h;
        lb[c] = __float2bfloat16(o[c] - __bfloat162float(h));
    }
    *(uint2*)(g_uHi + row * 1024 + j) = *(uint2*)hb;
    *(uint2*)(g_uLo + row * 1024 + j) = *(uint2*)lb;
}

__global__ void k_setx(const float* __restrict__ st) {
    int i = blockIdx.x * blockDim.x + threadIdx.x;
    if (i < NR) g_x[i] = st[0];
}

// -------- weight splits --------
__global__ void k_split(const float* __restrict__ src, bf16* __restrict__ hi,
                        bf16* __restrict__ lo, int n) {
    int i = blockIdx.x * blockDim.x + threadIdx.x;
    if (i >= n) return;
    float x = src[i];
    bf16 h = __float2bfloat16(x);
    hi[i] = h;
    lo[i] = __float2bfloat16(x - __bfloat162float(h));
}
__global__ void k_splitWoT(const float* __restrict__ Wo1) {
    int i = blockIdx.x * blockDim.x + threadIdx.x;   // over 512*256
    if (i >= 512 * 256) return;
    int k = i >> 8, n = i & 255;
    float x = Wo1[i];
    bf16 h = __float2bfloat16(x);
    g_Wo1Hi[n * 512 + k] = h;
    g_Wo1Lo[n * 512 + k] = __float2bfloat16(x - __bfloat162float(h));
}
__global__ void k_splitW2T(const float* __restrict__ W2) {
    int i = blockIdx.x * blockDim.x + threadIdx.x;   // over 1024*512
    if (i >= 1024 * 512) return;
    int k = i >> 9, n = i & 511;
    float x = W2[i];
    bf16 h = __float2bfloat16(x);
    g_W2Hi[n * 1024 + k] = h;
    g_W2Lo[n * 1024 + k] = __float2bfloat16(x - __bfloat162float(h));
}
__global__ void k_splitW1T(const float* __restrict__ W1) {
    int i = blockIdx.x * blockDim.x + threadIdx.x;   // over 1024*192
    if (i >= 1024 * 192) return;
    int n = i / 192, k = i % 192;
    float x = (k < 160) ? W1[(size_t)k * 1024 + n] : 0.f;
    bf16 h = __float2bfloat16(x);
    g_W1Hi[i] = h;
    g_W1Lo[i] = __float2bfloat16(x - __bfloat162float(h));
}

// ============================ GRU step (mma.sync) ===========================
// SW128, K-chunk 64, double-buffered cp.async, 160KB smem, 512 threads.
// Warp = 32 rows x 16 j x 3 gates. MMA issue reordered BY TERM so same-acc
// dependencies are 12 instructions apart (no RAW stall chains).
#define GRU_SMEM (160 * 1024)

__device__ __forceinline__ void gru_copy(uint32_t sb, int c, int b, int bM, int bJ,
                                         int tid, const bf16* hiIn, const bf16* loIn) {
#pragma unroll
    for (int i = 0; i < 4; ++i) {            // A: 2048 segs of 16B
        int seg = tid + 512 * i, hl = seg >> 10, rem = seg & 1023, row = rem >> 3, s = rem & 7;
        const bf16* src = (hl ? loIn : hiIn) + (size_t)(bM * 128 + row) * 512 + c * 64 + s * 8;
        cpasync16(sb + b * 32768 + hl * 16384 + swz(row * 128 + s * 16), src);
    }
#pragma unroll
    for (int i = 0; i < 6; ++i) {            // B: 3072 segs of 16B
        int seg = tid + 512 * i;
        int hl = seg >= 1536 ? 1 : 0, rem = seg - hl * 1536, row = rem >> 3, s = rem & 7;
        int grow = (row >> 6) * 512 + bJ * 64 + (row & 63);
        const bf16* src = (hl ? g_WhhLo : g_WhhHi) + (size_t)grow * 512 + c * 64 + s * 8;
        cpasync16(sb + 65536 + b * 49152 + hl * 24576 + swz(row * 128 + s * 16), src);
    }
}

__global__ __launch_bounds__(512, 1) void k_gru_mma(
    const float* __restrict__ W_ih, const float* __restrict__ b_ih,
    const float* __restrict__ b_hh, int t)
{
    extern __shared__ char smem[];
    const bf16* hiIn  = (t & 1) ? g_hiB : g_hiA;
    const bf16* loIn  = (t & 1) ? g_loB : g_loA;
    bf16*       hiOut = (t & 1) ? g_hiA : g_hiB;
    bf16*       loOut = (t & 1) ? g_loA : g_loB;

    const int bJ = blockIdx.x, bM = blockIdx.y, tid = threadIdx.x;
    const int wid = tid >> 5, lane = tid & 31;
    const int mgrp = wid >> 2, ngrp = wid & 3;
    uint32_t sb = smem_u32(smem);

    float acc[3][2][2][4];
#pragma unroll
    for (int g = 0; g < 3; ++g)
#pragma unroll
        for (int mt = 0; mt < 2; ++mt)
#pragma unroll
            for (int nt = 0; nt < 2; ++nt)
#pragma unroll
                for (int c = 0; c < 4; ++c) acc[g][mt][nt][c] = 0.f;

    gru_copy(sb, 0, 0, bM, bJ, tid, hiIn, loIn);
    CP_COMMIT();

    for (int c = 0; c < 8; ++c) {
        int b = c & 1;
        if (c + 1 < 8) { gru_copy(sb, c + 1, b ^ 1, bM, bJ, tid, hiIn, loIn); CP_COMMIT(); CP_WAIT1(); }
        else CP_WAIT0();
        __syncthreads();
#pragma unroll
        for (int ks = 0; ks < 4; ++ks) {
            uint32_t aH[2][4], aL[2][4], bH[3][4], bL[3][4];
#pragma unroll
            for (int mt = 0; mt < 2; ++mt) {
                int arow = mgrp * 32 + mt * 16 + (lane & 15);
                uint32_t off = swz(arow * 128 + ks * 32 + (lane >> 4) * 16);
                ldmx4(aH[mt], sb + b * 32768 + off);
                ldmx4(aL[mt], sb + b * 32768 + 16384 + off);
            }
#pragma unroll
            for (int g = 0; g < 3; ++g) {
                int brow = g * 64 + ngrp * 16 + (lane & 7) + ((lane >> 4) & 1) * 8;
                uint32_t boff = swz(brow * 128 + ks * 32 + ((lane >> 3) & 1) * 16);
                ldmx4(bH[g], sb + 65536 + b * 49152 + boff);
                ldmx4(bL[g], sb + 65536 + b * 49152 + 24576 + boff);
            }
            // term pass 1: Ahi * Bhi (12 independent accs)
#pragma unroll
            for (int g = 0; g < 3; ++g)
#pragma unroll
                for (int mt = 0; mt < 2; ++mt)
#pragma unroll
                    for (int nt = 0; nt < 2; ++nt)
                        mma_bf16(acc[g][mt][nt], aH[mt], bH[g] + nt * 2);
            // term pass 2: Ahi * Blo
#pragma unroll
            for (int g = 0; g < 3; ++g)
#pragma unroll
                for (int mt = 0; mt < 2; ++mt)
#pragma unroll
                    for (int nt = 0; nt < 2; ++nt)
                        mma_bf16(acc[g][mt][nt], aH[mt], bL[g] + nt * 2);
            // term pass 3: Alo * Bhi
#pragma unroll
            for (int g = 0; g < 3; ++g)
#pragma unroll
                for (int mt = 0; mt < 2; ++mt)
#pragma unroll
                    for (int nt = 0; nt < 2; ++nt)
                        mma_bf16(acc[g][mt][nt], aL[mt], bH[g] + nt * 2);
        }
        __syncthreads();
    }

    // ---- in-register gate epilogue (h_old reconstructed from hi/lo) ----
#pragma unroll
    for (int nt = 0; nt < 2; ++nt) {
        const int j = bJ * 64 + ngrp * 16 + nt * 8 + (lane & 3) * 2;
        float wih[3][2], bih[3][2], bhh[3][2];
#pragma unroll
        for (int g = 0; g < 3; ++g)
#pragma unroll
            for (int cc = 0; cc < 2; ++cc) {
                wih[g][cc] = W_ih[g * 512 + j + cc];
                bih[g][cc] = b_ih[g * 512 + j + cc];
                bhh[g][cc] = b_hh[g * 512 + j + cc];
            }
#pragma unroll
        for (int mt = 0; mt < 2; ++mt)
#pragma unroll
            for (int half = 0; half < 2; ++half) {
                int row = bM * 128 + mgrp * 32 + mt * 16 + (lane >> 2) + half * 8;
                float xi = g_x[row];
                __nv_bfloat162 h2 = *(const __nv_bfloat162*)(hiIn + (size_t)row * 512 + j);
                __nv_bfloat162 l2 = *(const __nv_bfloat162*)(loIn + (size_t)row * 512 + j);
                float hOld[2] = { __bfloat162float(h2.x) + __bfloat162float(l2.x),
                                  __bfloat162float(h2.y) + __bfloat162float(l2.y) };
                float hn[2];
#pragma unroll
                for (int cc = 0; cc < 2; ++cc) {
                    float ghr = acc[0][mt][nt][half * 2 + cc];
                    float ghz = acc[1][mt][nt][half * 2 + cc];
                    float ghn = acc[2][mt][nt][half * 2 + cc];
                    float rr = sig_(fmaf(xi, wih[0][cc], bih[0][cc]) + ghr + bhh[0][cc]);
                    float zz = sig_(fmaf(xi, wih[1][cc], bih[1][cc]) + ghz + bhh[1][cc]);
                    float nn = tanhf(fmaf(xi, wih[2][cc], bih[2][cc]) + rr * (ghn + bhh[2][cc]));
                    hn[cc] = (1.0f - zz) * nn + zz * hOld[cc];
                }
                bf16 h0 = __float2bfloat16(hn[0]), h1 = __float2bfloat16(hn[1]);
                __nv_bfloat162 hh; hh.x = h0; hh.y = h1;
                __nv_bfloat162 ll;
                ll.x = __float2bfloat16(hn[0] - __bfloat162float(h0));
                ll.y = __float2bfloat16(hn[1] - __bfloat162float(h1));
                *(__nv_bfloat162*)(hiOut + (size_t)row * 512 + j) = hh;
                *(__nv_bfloat162*)(loOut + (size_t)row * 512 + j) = ll;
            }
    }
}

// ============ generic 128-row x 64-col mma GEMM, term-reordered =============
// 256 threads, SW128, K-chunk 64, 96KB smem, warp = 64 rows x 16 n.
// MODE 0: write g_v[.,256]; MODE 1: tanh(acc+bias) -> g_hiA/g_loA[.,512];
// MODE 2: acc+bias -> g_u[.,1024] (fp32)
#define MMA64_SMEM (96 * 1024)

__device__ __forceinline__ void mma64_copy(uint32_t sb, int c, int b, int bM, int bJ,
                                           int tid, const bf16* aHi, const bf16* aLo,
                                           const bf16* bHi, const bf16* bLo, int K) {
#pragma unroll
    for (int i = 0; i < 8; ++i) {            // A: 2048 segs
        int seg = tid + 256 * i, hl = seg >> 10, rem = seg & 1023, row = rem >> 3, s = rem & 7;
        const bf16* src = (hl ? aLo : aHi) + (size_t)(bM * 128 + row) * K + c * 64 + s * 8;
        cpasync16(sb + b * 32768 + hl * 16384 + swz(row * 128 + s * 16), src);
    }
#pragma unroll
    for (int i = 0; i < 4; ++i) {            // B: 1024 segs
        int seg = tid + 256 * i, hl = seg >> 9, rem = seg & 511, row = rem >> 3, s = rem & 7;
        const bf16* src = (hl ? bLo : bHi) + (size_t)(bJ * 64 + row) * K + c * 64 + s * 8;
        cpasync16(sb + 65536 + b * 16384 + hl * 8192 + swz(row * 128 + s * 16), src);
    }
}

template <int KDIM, int MODE>
__global__ __launch_bounds__(256, 1) void k_mma64(
    const bf16* __restrict__ aHi, const bf16* __restrict__ aLo,
    const bf16* __restrict__ bHi, const bf16* __restrict__ bLo,
    const float* __restrict__ bias)
{
    extern __shared__ char smem[];
    const int bJ = blockIdx.x, bM = blockIdx.y, tid = threadIdx.x;
    const int wid = tid >> 5, lane = tid & 31;
    const int mgrp = wid >> 2, ngrp = wid & 3;
    uint32_t sb = smem_u32(smem);
    const int NCH = KDIM / 64;

    float acc[4][2][4];
#pragma unroll
    for (int mt = 0; mt < 4; ++mt)
#pragma unroll
        for (int nt = 0; nt < 2; ++nt)
#pragma unroll
            for (int c = 0; c < 4; ++c) acc[mt][nt][c] = 0.f;

    mma64_copy(sb, 0, 0, bM, bJ, tid, aHi, aLo, bHi, bLo, KDIM);
    CP_COMMIT();

    for (int c = 0; c < NCH; ++c) {
        int b = c & 1;
        if (c + 1 < NCH) { mma64_copy(sb, c + 1, b ^ 1, bM, bJ, tid, aHi, aLo, bHi, bLo, KDIM);
                           CP_COMMIT(); CP_WAIT1(); }
        else CP_WAIT0();
        __syncthreads();
#pragma unroll
        for (int ks = 0; ks < 4; ++ks) {
            uint32_t aH[4][4], aL[4][4], bH[4], bL[4];
#pragma unroll
            for (int mt = 0; mt < 4; ++mt) {
                int arow = mgrp * 64 + mt * 16 + (lane & 15);
                uint32_t off = swz(arow * 128 + ks * 32 + (lane >> 4) * 16);
                ldmx4(aH[mt], sb + b * 32768 + off);
                ldmx4(aL[mt], sb + b * 32768 + 16384 + off);
            }
            int brow = ngrp * 16 + (lane & 7) + ((lane >> 4) & 1) * 8;
            uint32_t boff = swz(brow * 128 + ks * 32 + ((lane >> 3) & 1) * 16);
            ldmx4(bH, sb + 65536 + b * 16384 + boff);
            ldmx4(bL, sb + 65536 + b * 16384 + 8192 + boff);
            // term-grouped passes (8 independent accs apart)
#pragma unroll
            for (int mt = 0; mt < 4; ++mt)
#pragma unroll
                for (int nt = 0; nt < 2; ++nt)
                    mma_bf16(acc[mt][nt], aH[mt], bH + nt * 2);
#pragma unroll
            for (int mt = 0; mt < 4; ++mt)
#pragma unroll
                for (int nt = 0; nt < 2; ++nt)
                    mma_bf16(acc[mt][nt], aH[mt], bL + nt * 2);
#pragma unroll
            for (int mt = 0; mt < 4; ++mt)
#pragma unroll
                for (int nt = 0; nt < 2; ++nt)
                    mma_bf16(acc[mt][nt], aL[mt], bH + nt * 2);
        }
        __syncthreads();
    }

#pragma unroll
    for (int nt = 0; nt < 2; ++nt) {
        const int n = bJ * 64 + ngrp * 16 + nt * 8 + (lane & 3) * 2;
#pragma unroll
        for (int mt = 0; mt < 4; ++mt)
#pragma unroll
            for (int half = 0; half < 2; ++half) {
                int row = bM * 128 + mgrp * 64 + mt * 16 + (lane >> 2) + half * 8;
                if (MODE == 0) {
                    *(float2*)(g_v + (size_t)row * 256 + n) =
                        make_float2(acc[mt][nt][half * 2], acc[mt][nt][half * 2 + 1]);
                } else if (MODE == 1) {
                    float hn0 = tanhf(acc[mt][nt][half * 2]     + bias[n]);
                    float hn1 = tanhf(acc[mt][nt][half * 2 + 1] + bias[n + 1]);
                    bf16 h0 = __float2bfloat16(hn0), h1 = __float2bfloat16(hn1);
                    __nv_bfloat162 hh; hh.x = h0; hh.y = h1;
                    __nv_bfloat162 ll;
                    ll.x = __float2bfloat16(hn0 - __bfloat162float(h0));
                    ll.y = __float2bfloat16(hn1 - __bfloat162float(h1));
                    *(__nv_bfloat162*)(g_hiA + (size_t)row * 512 + n) = hh;
                    *(__nv_bfloat162*)(g_loA + (size_t)row * 512 + n) = ll;
                } else {
                    *(float2*)(g_u + (size_t)row * 1024 + n) =
                        make_float2(acc[mt][nt][half * 2] + bias[n],
                                    acc[mt][nt][half * 2 + 1] + bias[n + 1]);
                }
            }
    }
}

// --------- output finalize: LN + GELU + dot(Wo2) + bias -> out, x ----------
__global__ __launch_bounds__(256) void k_outfin(
    const float* __restrict__ bo1, const float* __restrict__ go,
    const float* __restrict__ beo, const float* __restrict__ Wo2,
    const float* __restrict__ bo2, float* __restrict__ out, int t)
{
    const int tid = threadIdx.x, wid = tid >> 5, lane = tid & 31;
    const int row = blockIdx.x * 8 + wid;
    const float* vr = g_v + (size_t)row * 256 + lane * 8;
    float v[8];
    float4 a = *(const float4*)vr, b = *(const float4*)(vr + 4);
    v[0]=a.x; v[1]=a.y; v[2]=a.z; v[3]=a.w; v[4]=b.x; v[5]=b.y; v[6]=b.z; v[7]=b.w;
    const int j0 = lane * 8;
    float s = 0.f;
#pragma unroll
    for (int c = 0; c < 8; ++c) { v[c] += bo1[j0 + c]; s += v[c]; }
#pragma unroll
    for (int m = 16; m >= 1; m >>= 1) s += __shfl_xor_sync(~0u, s, m);
    float mean = s * (1.0f / 256.0f);
    float q = 0.f;
#pragma unroll
    for (int c = 0; c < 8; ++c) { float d = v[c] - mean; q += d * d; }
#pragma unroll
    for (int m = 16; m >= 1; m >>= 1) q += __shfl_xor_sync(~0u, q, m);
    float rstd = rsqrtf(q * (1.0f / 256.0f) + 1e-5f);
    float y = 0.f;
#pragma unroll
    for (int c = 0; c < 8; ++c) {
        float ln = (v[c] - mean) * rstd * go[j0 + c] + beo[j0 + c];
        y += gelu_(ln) * Wo2[j0 + c];
    }
#pragma unroll
    for (int m = 16; m >= 1; m >>= 1) y += __shfl_xor_sync(~0u, y, m);
    if (lane == 0) {
        float yy = y + bo2[0];
        out[(size_t)row * 20 + t] = yy;
        g_x[row] = yy;
    }
}

// ================================== host ====================================
extern "C" void kernel_launch(void* const* d_in, const int* in_sizes, int n_in,
                              void* d_out, int out_size) {
    const float* z_q   = (const float*)d_in[0];
    const float* f_pr  = (const float*)d_in[1];
    const float* W1    = (const float*)d_in[2];
    const float* b1    = (const float*)d_in[3];
    const float* g1    = (const float*)d_in[4];
    const float* be1   = (const float*)d_in[5];
    const float* W2    = (const float*)d_in[6];
    const float* b2    = (const float*)d_in[7];
    const float* start = (const float*)d_in[8];
    const float* W_ih  = (const float*)d_in[9];
    const float* W_hh  = (const float*)d_in[10];
    const float* b_ih  = (const float*)d_in[11];
    const float* b_hh  = (const float*)d_in[12];
    const float* Wo1   = (const float*)d_in[13];
    const float* bo1   = (const float*)d_in[14];
    const float* go    = (const float*)d_in[15];
    const float* beo   = (const float*)d_in[16];
    const float* Wo2   = (const float*)d_in[17];
    const float* bo2   = (const float*)d_in[18];
    float* out = (float*)d_out;

    cudaFuncSetAttribute(k_gru_mma, cudaFuncAttributeMaxDynamicSharedMemorySize, GRU_SMEM);
    cudaFuncSetAttribute(k_mma64<512, 0>, cudaFuncAttributeMaxDynamicSharedMemorySize, MMA64_SMEM);
    cudaFuncSetAttribute(k_mma64<1024, 1>, cudaFuncAttributeMaxDynamicSharedMemorySize, MMA64_SMEM);
    cudaFuncSetAttribute(k_mma64<192, 2>, cudaFuncAttributeMaxDynamicSharedMemorySize, MMA64_SMEM);

    bf16 *cHiP, *cLoP, *uHiP, *uLoP, *whhHiP, *whhLoP;
    bf16 *wo1HiP, *wo1LoP, *w2HiP, *w2LoP, *w1HiP, *w1LoP;
    bf16 *hiAP, *loAP, *hiBP, *loBP;
    cudaGetSymbolAddress((void**)&cHiP, g_cHi);
    cudaGetSymbolAddress((void**)&cLoP, g_cLo);
    cudaGetSymbolAddress((void**)&uHiP, g_uHi);
    cudaGetSymbolAddress((void**)&uLoP, g_uLo);
    cudaGetSymbolAddress((void**)&whhHiP, g_WhhHi);
    cudaGetSymbolAddress((void**)&whhLoP, g_WhhLo);
    cudaGetSymbolAddress((void**)&wo1HiP, g_Wo1Hi);
    cudaGetSymbolAddress((void**)&wo1LoP, g_Wo1Lo);
    cudaGetSymbolAddress((void**)&w2HiP, g_W2Hi);
    cudaGetSymbolAddress((void**)&w2LoP, g_W2Lo);
    cudaGetSymbolAddress((void**)&w1HiP, g_W1Hi);
    cudaGetSymbolAddress((void**)&w1LoP, g_W1Lo);
    cudaGetSymbolAddress((void**)&hiAP, g_hiA);
    cudaGetSymbolAddress((void**)&loAP, g_loA);
    cudaGetSymbolAddress((void**)&hiBP, g_hiB);
    cudaGetSymbolAddress((void**)&loBP, g_loB);

    // weight prep
    k_split<<<(1536 * 512 + 255) / 256, 256>>>(W_hh, whhHiP, whhLoP, 1536 * 512);
    k_splitWoT<<<(512 * 256 + 255) / 256, 256>>>(Wo1);
    k_splitW2T<<<(1024 * 512 + 255) / 256, 256>>>(W2);
    k_splitW1T<<<(1024 * 192 + 255) / 256, 256>>>(W1);

    // init MLP (all GEMMs on mma path)
    k_prep<<<(int)(((size_t)NR * 192 + 255) / 256), 256>>>(z_q, f_pr);
    k_mma64<192, 2><<<dim3(16, NR / 128), 256, MMA64_SMEM>>>(cHiP, cLoP, w1HiP, w1LoP, b1);
    k_lngelu<<<NR, 256>>>(g1, be1);
    k_mma64<1024, 1><<<dim3(8, NR / 128), 256, MMA64_SMEM>>>(uHiP, uLoP, w2HiP, w2LoP, b2);
    k_setx<<<NR / 256, 256>>>(start);

    // recurrence
    for (int t = 0; t < 20; ++t) {
        k_gru_mma<<<dim3(8, NR / 128), 512, GRU_SMEM>>>(W_ih, b_ih, b_hh, t);
        const bf16* hN = (t & 1) ? hiAP : hiBP;
        const bf16* lN = (t & 1) ? loAP : loBP;
        k_mma64<512, 0><<<dim3(4, NR / 128), 256, MMA64_SMEM>>>(hN, lN, wo1HiP, wo1LoP, nullptr);
        k_outfin<<<NR / 8, 256>>>(bo1, go, beo, Wo2, bo2, out, t);
    }
}

// round 11
// speedup vs baseline: 1.2965x; 1.2965x over previous
#include <cuda_runtime.h>
#include <cuda_fp16.h>
#include <cstdint>

#define NR 65536
typedef __half fp16;

// ----------------------------- device scratch ------------------------------
__device__ float g_u[(size_t)NR * 1024];
__device__ fp16  g_cHi[(size_t)NR * 192];    // concat(z,f) padded to K=192
__device__ fp16  g_uHi[(size_t)NR * 1024];
__device__ fp16  g_hiA[(size_t)NR * 512];
__device__ fp16  g_loA[(size_t)NR * 512];
__device__ fp16  g_hiB[(size_t)NR * 512];
__device__ fp16  g_loB[(size_t)NR * 512];
__device__ float g_v[(size_t)NR * 256];
__device__ float g_x[NR];
__device__ fp16  g_WhhHi[1536 * 512];
__device__ fp16  g_WhhLo[1536 * 512];
__device__ fp16  g_Wo1Hi[256 * 512];     // transposed [N=256, K=512]
__device__ fp16  g_Wo1Lo[256 * 512];
__device__ fp16  g_W2Hi[512 * 1024];     // transposed [N=512, K=1024]
__device__ fp16  g_W2Lo[512 * 1024];
__device__ fp16  g_W1Hi[1024 * 192];     // transposed+padded [N=1024, K=192]
__device__ fp16  g_W1Lo[1024 * 192];

// ----------------------------- small helpers -------------------------------
__device__ __forceinline__ float sig_(float x) { return 1.0f / (1.0f + expf(-x)); }
__device__ __forceinline__ float gelu_(float x) {
    return 0.5f * x * (1.0f + erff(x * 0.70710678f));
}
__device__ __forceinline__ uint32_t smem_u32(const void* p) {
    uint32_t a;
    asm("{ .reg .u64 t; cvta.to.shared.u64 t, %1; cvt.u32.u64 %0, t; }" : "=r"(a) : "l"(p));
    return a;
}
__device__ __forceinline__ uint32_t swz(uint32_t off) { return off ^ ((off >> 3) & 0x70); }

__device__ __forceinline__ void cpasync16(uint32_t saddr, const void* gptr) {
    asm volatile("{ .reg .u64 g; cvta.to.global.u64 g, %1; "
                 "cp.async.cg.shared.global [%0], [g], 16; }"
                 :: "r"(saddr), "l"(gptr) : "memory");
}
#define CP_COMMIT() asm volatile("cp.async.commit_group;" ::: "memory")
#define CP_WAIT1()  asm volatile("cp.async.wait_group 1;" ::: "memory")
#define CP_WAIT0()  asm volatile("cp.async.wait_group 0;" ::: "memory")

__device__ __forceinline__ void ldmx4(uint32_t* r, uint32_t addr) {
    asm volatile("ldmatrix.sync.aligned.m8n8.x4.shared.b16 {%0,%1,%2,%3}, [%4];"
        : "=r"(r[0]), "=r"(r[1]), "=r"(r[2]), "=r"(r[3]) : "r"(addr));
}
__device__ __forceinline__ void mma_fp16(float* d, const uint32_t* a, const uint32_t* b) {
    asm volatile("mma.sync.aligned.m16n8k16.row.col.f32.f16.f16.f32 "
        "{%0,%1,%2,%3}, {%4,%5,%6,%7}, {%8,%9}, {%0,%1,%2,%3};"
        : "+f"(d[0]), "+f"(d[1]), "+f"(d[2]), "+f"(d[3])
        : "r"(a[0]), "r"(a[1]), "r"(a[2]), "r"(a[3]), "r"(b[0]), "r"(b[1]));
}

// =========================== init-path kernels =============================
// concat(z,f) -> single fp16 plane, K padded 160 -> 192 with zeros
__global__ void k_prep(const float* __restrict__ z, const float* __restrict__ f) {
    size_t i = (size_t)blockIdx.x * blockDim.x + threadIdx.x;
    if (i >= (size_t)NR * 192) return;
    int row = (int)(i / 192), col = (int)(i % 192);
    float x = (col < 128) ? z[(size_t)row * 128 + col]
            : (col < 160) ? f[(size_t)row * 32 + col - 128] : 0.f;
    g_cHi[i] = __float2half_rn(x);
}

// u -> gelu(LN(u)), written as a single fp16 plane
__global__ __launch_bounds__(256) void k_lngelu(
    const float* __restrict__ g1, const float* __restrict__ be1)
{
    const size_t row = blockIdx.x;
    const int tid = threadIdx.x, lane = tid & 31, w = tid >> 5;
    const float* up = g_u + row * 1024 + tid * 4;
    float4 v = *(const float4*)up;
    __shared__ float red[8];
    float s = v.x + v.y + v.z + v.w;
#pragma unroll
    for (int m = 16; m >= 1; m >>= 1) s += __shfl_xor_sync(~0u, s, m);
    if (lane == 0) red[w] = s;
    __syncthreads();
    float tot = 0.f;
#pragma unroll
    for (int i = 0; i < 8; ++i) tot += red[i];
    const float mean = tot * (1.0f / 1024.0f);
    float dx = v.x - mean, dy = v.y - mean, dz = v.z - mean, dw = v.w - mean;
    float q = dx * dx + dy * dy + dz * dz + dw * dw;
#pragma unroll
    for (int m = 16; m >= 1; m >>= 1) q += __shfl_xor_sync(~0u, q, m);
    __syncthreads();
    if (lane == 0) red[w] = q;
    __syncthreads();
    float qt = 0.f;
#pragma unroll
    for (int i = 0; i < 8; ++i) qt += red[i];
    const float rstd = rsqrtf(qt * (1.0f / 1024.0f) + 1e-5f);
    const int j = tid * 4;
    float4 g4 = *(const float4*)&g1[j];
    float4 b4 = *(const float4*)&be1[j];
    __align__(8) fp16 hb[4];
    hb[0] = __float2half_rn(gelu_(dx * rstd * g4.x + b4.x));
    hb[1] = __float2half_rn(gelu_(dy * rstd * g4.y + b4.y));
    hb[2] = __float2half_rn(gelu_(dz * rstd * g4.z + b4.z));
    hb[3] = __float2half_rn(gelu_(dw * rstd * g4.w + b4.w));
    *(uint2*)(g_uHi + row * 1024 + j) = *(uint2*)hb;
}

__global__ void k_setx(const float* __restrict__ st) {
    int i = blockIdx.x * blockDim.x + threadIdx.x;
    if (i < NR) g_x[i] = st[0];
}

// -------- weight splits (fp16 hi/lo) --------
__global__ void k_splitWhh(const float* __restrict__ W_hh) {
    int i = blockIdx.x * blockDim.x + threadIdx.x;
    if (i >= 1536 * 512) return;
    float x = W_hh[i];
    fp16 h = __float2half_rn(x);
    g_WhhHi[i] = h;
    g_WhhLo[i] = __float2half_rn(x - __half2float(h));
}
__global__ void k_splitWoT(const float* __restrict__ Wo1) {
    int i = blockIdx.x * blockDim.x + threadIdx.x;   // over 512*256
    if (i >= 512 * 256) return;
    int k = i >> 8, n = i & 255;
    float x = Wo1[i];
    fp16 h = __float2half_rn(x);
    g_Wo1Hi[n * 512 + k] = h;
    g_Wo1Lo[n * 512 + k] = __float2half_rn(x - __half2float(h));
}
__global__ void k_splitW2T(const float* __restrict__ W2) {
    int i = blockIdx.x * blockDim.x + threadIdx.x;   // over 1024*512
    if (i >= 1024 * 512) return;
    int k = i >> 9, n = i & 511;
    float x = W2[i];
    fp16 h = __float2half_rn(x);
    g_W2Hi[n * 1024 + k] = h;
    g_W2Lo[n * 1024 + k] = __float2half_rn(x - __half2float(h));
}
__global__ void k_splitW1T(const float* __restrict__ W1) {
    int i = blockIdx.x * blockDim.x + threadIdx.x;   // over 1024*192
    if (i >= 1024 * 192) return;
    int n = i / 192, k = i % 192;
    float x = (k < 160) ? W1[(size_t)k * 1024 + n] : 0.f;
    fp16 h = __float2half_rn(x);
    g_W1Hi[i] = h;
    g_W1Lo[i] = __float2half_rn(x - __half2float(h));
}

// ============================ GRU step (mma.sync) ===========================
// fp16 2-term: A (state hi plane only) x (Bhi + Blo weight planes).
// SW128, K-chunk 64, double-buffered cp.async, 128KB smem, 512 threads.
// SMEM: A[buf] @ b*16384 (128 rows x 128B); B[buf][hl] @ 32768 + b*49152 + hl*24576.
#define GRU_SMEM (128 * 1024)

__device__ __forceinline__ void gru_copy(uint32_t sb, int c, int b, int bM, int bJ,
                                         int tid, const fp16* hiIn) {
#pragma unroll
    for (int i = 0; i < 2; ++i) {            // A: 1024 segs of 16B
        int seg = tid + 512 * i, row = seg >> 3, s = seg & 7;
        const fp16* src = hiIn + (size_t)(bM * 128 + row) * 512 + c * 64 + s * 8;
        cpasync16(sb + b * 16384 + swz(row * 128 + s * 16), src);
    }
#pragma unroll
    for (int i = 0; i < 6; ++i) {            // B: 3072 segs of 16B
        int seg = tid + 512 * i;
        int hl = seg >= 1536 ? 1 : 0, rem = seg - hl * 1536, row = rem >> 3, s = rem & 7;
        int grow = (row >> 6) * 512 + bJ * 64 + (row & 63);
        const fp16* src = (hl ? g_WhhLo : g_WhhHi) + (size_t)grow * 512 + c * 64 + s * 8;
        cpasync16(sb + 32768 + b * 49152 + hl * 24576 + swz(row * 128 + s * 16), src);
    }
}

__global__ __launch_bounds__(512, 1) void k_gru_mma(
    const float* __restrict__ W_ih, const float* __restrict__ b_ih,
    const float* __restrict__ b_hh, int t)
{
    extern __shared__ char smem[];
    const fp16* hiIn  = (t & 1) ? g_hiB : g_hiA;
    const fp16* loIn  = (t & 1) ? g_loB : g_loA;
    fp16*       hiOut = (t & 1) ? g_hiA : g_hiB;
    fp16*       loOut = (t & 1) ? g_loA : g_loB;

    const int bJ = blockIdx.x, bM = blockIdx.y, tid = threadIdx.x;
    const int wid = tid >> 5, lane = tid & 31;
    const int mgrp = wid >> 2, ngrp = wid & 3;
    uint32_t sb = smem_u32(smem);

    float acc[3][2][2][4];
#pragma unroll
    for (int g = 0; g < 3; ++g)
#pragma unroll
        for (int mt = 0; mt < 2; ++mt)
#pragma unroll
            for (int nt = 0; nt < 2; ++nt)
#pragma unroll
                for (int c = 0; c < 4; ++c) acc[g][mt][nt][c] = 0.f;

    gru_copy(sb, 0, 0, bM, bJ, tid, hiIn);
    CP_COMMIT();

    for (int c = 0; c < 8; ++c) {
        int b = c & 1;
        if (c + 1 < 8) { gru_copy(sb, c + 1, b ^ 1, bM, bJ, tid, hiIn); CP_COMMIT(); CP_WAIT1(); }
        else CP_WAIT0();
        __syncthreads();
#pragma unroll
        for (int ks = 0; ks < 4; ++ks) {
            uint32_t aH[2][4], bH[3][4], bL[3][4];
#pragma unroll
            for (int mt = 0; mt < 2; ++mt) {
                int arow = mgrp * 32 + mt * 16 + (lane & 15);
                uint32_t off = swz(arow * 128 + ks * 32 + (lane >> 4) * 16);
                ldmx4(aH[mt], sb + b * 16384 + off);
            }
#pragma unroll
            for (int g = 0; g < 3; ++g) {
                int brow = g * 64 + ngrp * 16 + (lane & 7) + ((lane >> 4) & 1) * 8;
                uint32_t boff = swz(brow * 128 + ks * 32 + ((lane >> 3) & 1) * 16);
                ldmx4(bH[g], sb + 32768 + b * 49152 + boff);
                ldmx4(bL[g], sb + 32768 + b * 49152 + 24576 + boff);
            }
            // term pass 1: A * Bhi (12 independent accs)
#pragma unroll
            for (int g = 0; g < 3; ++g)
#pragma unroll
                for (int mt = 0; mt < 2; ++mt)
#pragma unroll
                    for (int nt = 0; nt < 2; ++nt)
                        mma_fp16(acc[g][mt][nt], aH[mt], bH[g] + nt * 2);
            // term pass 2: A * Blo
#pragma unroll
            for (int g = 0; g < 3; ++g)
#pragma unroll
                for (int mt = 0; mt < 2; ++mt)
#pragma unroll
                    for (int nt = 0; nt < 2; ++nt)
                        mma_fp16(acc[g][mt][nt], aH[mt], bL[g] + nt * 2);
        }
        __syncthreads();
    }

    // ---- in-register gate epilogue (h_old reconstructed from hi/lo) ----
#pragma unroll
    for (int nt = 0; nt < 2; ++nt) {
        const int j = bJ * 64 + ngrp * 16 + nt * 8 + (lane & 3) * 2;
        float wih[3][2], bih[3][2], bhh[3][2];
#pragma unroll
        for (int g = 0; g < 3; ++g)
#pragma unroll
            for (int cc = 0; cc < 2; ++cc) {
                wih[g][cc] = W_ih[g * 512 + j + cc];
                bih[g][cc] = b_ih[g * 512 + j + cc];
                bhh[g][cc] = b_hh[g * 512 + j + cc];
            }
#pragma unroll
        for (int mt = 0; mt < 2; ++mt)
#pragma unroll
            for (int half = 0; half < 2; ++half) {
                int row = bM * 128 + mgrp * 32 + mt * 16 + (lane >> 2) + half * 8;
                float xi = g_x[row];
                __half2 h2 = *(const __half2*)(hiIn + (size_t)row * 512 + j);
                __half2 l2 = *(const __half2*)(loIn + (size_t)row * 512 + j);
                float hOld[2] = { __half2float(h2.x) + __half2float(l2.x),
                                  __half2float(h2.y) + __half2float(l2.y) };
                float hn[2];
#pragma unroll
                for (int cc = 0; cc < 2; ++cc) {
                    float ghr = acc[0][mt][nt][half * 2 + cc];
                    float ghz = acc[1][mt][nt][half * 2 + cc];
                    float ghn = acc[2][mt][nt][half * 2 + cc];
                    float rr = sig_(fmaf(xi, wih[0][cc], bih[0][cc]) + ghr + bhh[0][cc]);
                    float zz = sig_(fmaf(xi, wih[1][cc], bih[1][cc]) + ghz + bhh[1][cc]);
                    float nn = tanhf(fmaf(xi, wih[2][cc], bih[2][cc]) + rr * (ghn + bhh[2][cc]));
                    hn[cc] = (1.0f - zz) * nn + zz * hOld[cc];
                }
                fp16 h0 = __float2half_rn(hn[0]), h1 = __float2half_rn(hn[1]);
                __half2 hh; hh.x = h0; hh.y = h1;
                __half2 ll;
                ll.x = __float2half_rn(hn[0] - __half2float(h0));
                ll.y = __float2half_rn(hn[1] - __half2float(h1));
                *(__half2*)(hiOut + (size_t)row * 512 + j) = hh;
                *(__half2*)(loOut + (size_t)row * 512 + j) = ll;
            }
    }
}

// ======== generic 128-row x 64-col fp16 2-term mma GEMM =====================
// 256 threads, SW128, K-chunk 64, 64KB smem (2 CTAs/SM), warp = 64 rows x 16 n.
// MODE 0: write g_v[.,256]; MODE 1: tanh(acc+bias) -> g_hiA/g_loA[.,512];
// MODE 2: acc+bias -> g_u[.,1024] (fp32)
#define MMA64_SMEM (64 * 1024)

__device__ __forceinline__ void mma64_copy(uint32_t sb, int c, int b, int bM, int bJ,
                                           int tid, const fp16* aHi,
                                           const fp16* bHi, const fp16* bLo, int K) {
#pragma unroll
    for (int i = 0; i < 4; ++i) {            // A: 1024 segs
        int seg = tid + 256 * i, row = seg >> 3, s = seg & 7;
        const fp16* src = aHi + (size_t)(bM * 128 + row) * K + c * 64 + s * 8;
        cpasync16(sb + b * 16384 + swz(row * 128 + s * 16), src);
    }
#pragma unroll
    for (int i = 0; i < 4; ++i) {            // B: 1024 segs (2 planes x 64 rows)
        int seg = tid + 256 * i, hl = seg >> 9, rem = seg & 511, row = rem >> 3, s = rem & 7;
        const fp16* src = (hl ? bLo : bHi) + (size_t)(bJ * 64 + row) * K + c * 64 + s * 8;
        cpasync16(sb + 32768 + b * 16384 + hl * 8192 + swz(row * 128 + s * 16), src);
    }
}

template <int KDIM, int MODE>
__global__ __launch_bounds__(256, 2) void k_mma64(
    const fp16* __restrict__ aHi,
    const fp16* __restrict__ bHi, const fp16* __restrict__ bLo,
    const float* __restrict__ bias)
{
    extern __shared__ char smem[];
    const int bJ = blockIdx.x, bM = blockIdx.y, tid = threadIdx.x;
    const int wid = tid >> 5, lane = tid & 31;
    const int mgrp = wid >> 2, ngrp = wid & 3;
    uint32_t sb = smem_u32(smem);
    const int NCH = KDIM / 64;

    float acc[4][2][4];
#pragma unroll
    for (int mt = 0; mt < 4; ++mt)
#pragma unroll
        for (int nt = 0; nt < 2; ++nt)
#pragma unroll
            for (int c = 0; c < 4; ++c) acc[mt][nt][c] = 0.f;

    mma64_copy(sb, 0, 0, bM, bJ, tid, aHi, bHi, bLo, KDIM);
    CP_COMMIT();

    for (int c = 0; c < NCH; ++c) {
        int b = c & 1;
        if (c + 1 < NCH) { mma64_copy(sb, c + 1, b ^ 1, bM, bJ, tid, aHi, bHi, bLo, KDIM);
                           CP_COMMIT(); CP_WAIT1(); }
        else CP_WAIT0();
        __syncthreads();
#pragma unroll
        for (int ks = 0; ks < 4; ++ks) {
            uint32_t aH[4][4], bH[4], bL[4];
#pragma unroll
            for (int mt = 0; mt < 4; ++mt) {
                int arow = mgrp * 64 + mt * 16 + (lane & 15);
                uint32_t off = swz(arow * 128 + ks * 32 + (lane >> 4) * 16);
                ldmx4(aH[mt], sb + b * 16384 + off);
            }
            int brow = ngrp * 16 + (lane & 7) + ((lane >> 4) & 1) * 8;
            uint32_t boff = swz(brow * 128 + ks * 32 + ((lane >> 3) & 1) * 16);
            ldmx4(bH, sb + 32768 + b * 16384 + boff);
            ldmx4(bL, sb + 32768 + b * 16384 + 8192 + boff);
#pragma unroll
            for (int mt = 0; mt < 4; ++mt)
#pragma unroll
                for (int nt = 0; nt < 2; ++nt)
                    mma_fp16(acc[mt][nt], aH[mt], bH + nt * 2);
#pragma unroll
            for (int mt = 0; mt < 4; ++mt)
#pragma unroll
                for (int nt = 0; nt < 2; ++nt)
                    mma_fp16(acc[mt][nt], aH[mt], bL + nt * 2);
        }
        __syncthreads();
    }

#pragma unroll
    for (int nt = 0; nt < 2; ++nt) {
        const int n = bJ * 64 + ngrp * 16 + nt * 8 + (lane & 3) * 2;
#pragma unroll
        for (int mt = 0; mt < 4; ++mt)
#pragma unroll
            for (int half = 0; half < 2; ++half) {
                int row = bM * 128 + mgrp * 64 + mt * 16 + (lane >> 2) + half * 8;
                if (MODE == 0) {
                    *(float2*)(g_v + (size_t)row * 256 + n) =
                        make_float2(acc[mt][nt][half * 2], acc[mt][nt][half * 2 + 1]);
                } else if (MODE == 1) {
                    float hn0 = tanhf(acc[mt][nt][half * 2]     + bias[n]);
                    float hn1 = tanhf(acc[mt][nt][half * 2 + 1] + bias[n + 1]);
                    fp16 h0 = __float2half_rn(hn0), h1 = __float2half_rn(hn1);
                    __half2 hh; hh.x = h0; hh.y = h1;
                    __half2 ll;
                    ll.x = __float2half_rn(hn0 - __half2float(h0));
                    ll.y = __float2half_rn(hn1 - __half2float(h1));
                    *(__half2*)(g_hiA + (size_t)row * 512 + n) = hh;
                    *(__half2*)(g_loA + (size_t)row * 512 + n) = ll;
                } else {
                    *(float2*)(g_u + (size_t)row * 1024 + n) =
                        make_float2(acc[mt][nt][half * 2] + bias[n],
                                    acc[mt][nt][half * 2 + 1] + bias[n + 1]);
                }
            }
    }
}

// --------- output finalize: LN + GELU + dot(Wo2) + bias -> out, x ----------
__global__ __launch_bounds__(256) void k_outfin(
    const float* __restrict__ bo1, const float* __restrict__ go,
    const float* __restrict__ beo, const float* __restrict__ Wo2,
    const float* __restrict__ bo2, float* __restrict__ out, int t)
{
    const int tid = threadIdx.x, wid = tid >> 5, lane = tid & 31;
    const int row = blockIdx.x * 8 + wid;
    const float* vr = g_v + (size_t)row * 256 + lane * 8;
    float v[8];
    float4 a = *(const float4*)vr, b = *(const float4*)(vr + 4);
    v[0]=a.x; v[1]=a.y; v[2]=a.z; v[3]=a.w; v[4]=b.x; v[5]=b.y; v[6]=b.z; v[7]=b.w;
    const int j0 = lane * 8;
    float s = 0.f;
#pragma unroll
    for (int c = 0; c < 8; ++c) { v[c] += bo1[j0 + c]; s += v[c]; }
#pragma unroll
    for (int m = 16; m >= 1; m >>= 1) s += __shfl_xor_sync(~0u, s, m);
    float mean = s * (1.0f / 256.0f);
    float q = 0.f;
#pragma unroll
    for (int c = 0; c < 8; ++c) { float d = v[c] - mean; q += d * d; }
#pragma unroll
    for (int m = 16; m >= 1; m >>= 1) q += __shfl_xor_sync(~0u, q, m);
    float rstd = rsqrtf(q * (1.0f / 256.0f) + 1e-5f);
    float y = 0.f;
#pragma unroll
    for (int c = 0; c < 8; ++c) {
        float ln = (v[c] - mean) * rstd * go[j0 + c] + beo[j0 + c];
        y += gelu_(ln) * Wo2[j0 + c];
    }
#pragma unroll
    for (int m = 16; m >= 1; m >>= 1) y += __shfl_xor_sync(~0u, y, m);
    if (lane == 0) {
        float yy = y + bo2[0];
        out[(size_t)row * 20 + t] = yy;
        g_x[row] = yy;
    }
}

// ================================== host ====================================
extern "C" void kernel_launch(void* const* d_in, const int* in_sizes, int n_in,
                              void* d_out, int out_size) {
    const float* z_q   = (const float*)d_in[0];
    const float* f_pr  = (const float*)d_in[1];
    const float* W1    = (const float*)d_in[2];
    const float* b1    = (const float*)d_in[3];
    const float* g1    = (const float*)d_in[4];
    const float* be1   = (const float*)d_in[5];
    const float* W2    = (const float*)d_in[6];
    const float* b2    = (const float*)d_in[7];
    const float* start = (const float*)d_in[8];
    const float* W_ih  = (const float*)d_in[9];
    const float* W_hh  = (const float*)d_in[10];
    const float* b_ih  = (const float*)d_in[11];
    const float* b_hh  = (const float*)d_in[12];
    const float* Wo1   = (const float*)d_in[13];
    const float* bo1   = (const float*)d_in[14];
    const float* go    = (const float*)d_in[15];
    const float* beo   = (const float*)d_in[16];
    const float* Wo2   = (const float*)d_in[17];
    const float* bo2   = (const float*)d_in[18];
    float* out = (float*)d_out;

    cudaFuncSetAttribute(k_gru_mma, cudaFuncAttributeMaxDynamicSharedMemorySize, GRU_SMEM);
    cudaFuncSetAttribute(k_mma64<512, 0>, cudaFuncAttributeMaxDynamicSharedMemorySize, MMA64_SMEM);
    cudaFuncSetAttribute(k_mma64<1024, 1>, cudaFuncAttributeMaxDynamicSharedMemorySize, MMA64_SMEM);
    cudaFuncSetAttribute(k_mma64<192, 2>, cudaFuncAttributeMaxDynamicSharedMemorySize, MMA64_SMEM);

    fp16 *cHiP, *uHiP, *wo1HiP, *wo1LoP, *w2HiP, *w2LoP, *w1HiP, *w1LoP;
    fp16 *hiAP, *hiBP;
    cudaGetSymbolAddress((void**)&cHiP, g_cHi);
    cudaGetSymbolAddress((void**)&uHiP, g_uHi);
    cudaGetSymbolAddress((void**)&wo1HiP, g_Wo1Hi);
    cudaGetSymbolAddress((void**)&wo1LoP, g_Wo1Lo);
    cudaGetSymbolAddress((void**)&w2HiP, g_W2Hi);
    cudaGetSymbolAddress((void**)&w2LoP, g_W2Lo);
    cudaGetSymbolAddress((void**)&w1HiP, g_W1Hi);
    cudaGetSymbolAddress((void**)&w1LoP, g_W1Lo);
    cudaGetSymbolAddress((void**)&hiAP, g_hiA);
    cudaGetSymbolAddress((void**)&hiBP, g_hiB);

    // weight prep
    k_splitWhh<<<(1536 * 512 + 255) / 256, 256>>>(W_hh);
    k_splitWoT<<<(512 * 256 + 255) / 256, 256>>>(Wo1);
    k_splitW2T<<<(1024 * 512 + 255) / 256, 256>>>(W2);
    k_splitW1T<<<(1024 * 192 + 255) / 256, 256>>>(W1);

    // init MLP (all GEMMs on mma path)
    k_prep<<<(int)(((size_t)NR * 192 + 255) / 256), 256>>>(z_q, f_pr);
    k_mma64<192, 2><<<dim3(16, NR / 128), 256, MMA64_SMEM>>>(cHiP, w1HiP, w1LoP, b1);
    k_lngelu<<<NR, 256>>>(g1, be1);
    k_mma64<1024, 1><<<dim3(8, NR / 128), 256, MMA64_SMEM>>>(uHiP, w2HiP, w2LoP, b2);
    k_setx<<<NR / 256, 256>>>(start);

    // recurrence
    for (int t = 0; t < 20; ++t) {
        k_gru_mma<<<dim3(8, NR / 128), 512, GRU_SMEM>>>(W_ih, b_ih, b_hh, t);
        const fp16* hN = (t & 1) ? hiAP : hiBP;
        k_mma64<512, 0><<<dim3(4, NR / 128), 256, MMA64_SMEM>>>(hN, wo1HiP, wo1LoP, nullptr);
        k_outfin<<<NR / 8, 256>>>(bo1, go, beo, Wo2, bo2, out, t);
    }
}

// round 12
// speedup vs baseline: 1.4156x; 1.0919x over previous
#include <cuda_runtime.h>
#include <cuda_fp16.h>
#include <cstdint>

#define NR 65536
typedef __half fp16;

// ----------------------------- device scratch ------------------------------
__device__ float g_u[(size_t)NR * 1024];
__device__ fp16  g_cHi[(size_t)NR * 192];    // concat(z,f) padded to K=192
__device__ fp16  g_uHi[(size_t)NR * 1024];
__device__ fp16  g_hiA[(size_t)NR * 512];
__device__ fp16  g_loA[(size_t)NR * 512];
__device__ fp16  g_hiB[(size_t)NR * 512];
__device__ fp16  g_loB[(size_t)NR * 512];
__device__ float g_x[NR];
__device__ fp16  g_WhhHi[1536 * 512];
__device__ fp16  g_WhhLo[1536 * 512];
__device__ fp16  g_Wo1Hi[256 * 512];     // transposed [N=256, K=512], hi only
__device__ fp16  g_W2Hi[512 * 1024];     // transposed [N=512, K=1024]
__device__ fp16  g_W2Lo[512 * 1024];
__device__ fp16  g_W1Hi[1024 * 192];     // transposed+padded [N=1024, K=192]
__device__ fp16  g_W1Lo[1024 * 192];

// ----------------------------- small helpers -------------------------------
__device__ __forceinline__ float sig_(float x) { return 1.0f / (1.0f + expf(-x)); }
__device__ __forceinline__ float gelu_(float x) {
    return 0.5f * x * (1.0f + erff(x * 0.70710678f));
}
__device__ __forceinline__ uint32_t smem_u32(const void* p) {
    uint32_t a;
    asm("{ .reg .u64 t; cvta.to.shared.u64 t, %1; cvt.u32.u64 %0, t; }" : "=r"(a) : "l"(p));
    return a;
}
__device__ __forceinline__ uint32_t swz(uint32_t off) { return off ^ ((off >> 3) & 0x70); }

__device__ __forceinline__ void cpasync16(uint32_t saddr, const void* gptr) {
    asm volatile("{ .reg .u64 g; cvta.to.global.u64 g, %1; "
                 "cp.async.cg.shared.global [%0], [g], 16; }"
                 :: "r"(saddr), "l"(gptr) : "memory");
}
#define CP_COMMIT() asm volatile("cp.async.commit_group;" ::: "memory")
#define CP_WAIT1()  asm volatile("cp.async.wait_group 1;" ::: "memory")
#define CP_WAIT0()  asm volatile("cp.async.wait_group 0;" ::: "memory")

__device__ __forceinline__ void ldmx4(uint32_t* r, uint32_t addr) {
    asm volatile("ldmatrix.sync.aligned.m8n8.x4.shared.b16 {%0,%1,%2,%3}, [%4];"
        : "=r"(r[0]), "=r"(r[1]), "=r"(r[2]), "=r"(r[3]) : "r"(addr));
}
__device__ __forceinline__ void mma_fp16(float* d, const uint32_t* a, const uint32_t* b) {
    asm volatile("mma.sync.aligned.m16n8k16.row.col.f32.f16.f16.f32 "
        "{%0,%1,%2,%3}, {%4,%5,%6,%7}, {%8,%9}, {%0,%1,%2,%3};"
        : "+f"(d[0]), "+f"(d[1]), "+f"(d[2]), "+f"(d[3])
        : "r"(a[0]), "r"(a[1]), "r"(a[2]), "r"(a[3]), "r"(b[0]), "r"(b[1]));
}

// =========================== init-path kernels =============================
__global__ void k_prep(const float* __restrict__ z, const float* __restrict__ f) {
    size_t i = (size_t)blockIdx.x * blockDim.x + threadIdx.x;
    if (i >= (size_t)NR * 192) return;
    int row = (int)(i / 192), col = (int)(i % 192);
    float x = (col < 128) ? z[(size_t)row * 128 + col]
            : (col < 160) ? f[(size_t)row * 32 + col - 128] : 0.f;
    g_cHi[i] = __float2half_rn(x);
}

__global__ __launch_bounds__(256) void k_lngelu(
    const float* __restrict__ g1, const float* __restrict__ be1)
{
    const size_t row = blockIdx.x;
    const int tid = threadIdx.x, lane = tid & 31, w = tid >> 5;
    const float* up = g_u + row * 1024 + tid * 4;
    float4 v = *(const float4*)up;
    __shared__ float red[8];
    float s = v.x + v.y + v.z + v.w;
#pragma unroll
    for (int m = 16; m >= 1; m >>= 1) s += __shfl_xor_sync(~0u, s, m);
    if (lane == 0) red[w] = s;
    __syncthreads();
    float tot = 0.f;
#pragma unroll
    for (int i = 0; i < 8; ++i) tot += red[i];
    const float mean = tot * (1.0f / 1024.0f);
    float dx = v.x - mean, dy = v.y - mean, dz = v.z - mean, dw = v.w - mean;
    float q = dx * dx + dy * dy + dz * dz + dw * dw;
#pragma unroll
    for (int m = 16; m >= 1; m >>= 1) q += __shfl_xor_sync(~0u, q, m);
    __syncthreads();
    if (lane == 0) red[w] = q;
    __syncthreads();
    float qt = 0.f;
#pragma unroll
    for (int i = 0; i < 8; ++i) qt += red[i];
    const float rstd = rsqrtf(qt * (1.0f / 1024.0f) + 1e-5f);
    const int j = tid * 4;
    float4 g4 = *(const float4*)&g1[j];
    float4 b4 = *(const float4*)&be1[j];
    __align__(8) fp16 hb[4];
    hb[0] = __float2half_rn(gelu_(dx * rstd * g4.x + b4.x));
    hb[1] = __float2half_rn(gelu_(dy * rstd * g4.y + b4.y));
    hb[2] = __float2half_rn(gelu_(dz * rstd * g4.z + b4.z));
    hb[3] = __float2half_rn(gelu_(dw * rstd * g4.w + b4.w));
    *(uint2*)(g_uHi + row * 1024 + j) = *(uint2*)hb;
}

__global__ void k_setx(const float* __restrict__ st) {
    int i = blockIdx.x * blockDim.x + threadIdx.x;
    if (i < NR) g_x[i] = st[0];
}

// -------- weight splits --------
__global__ void k_splitWhh(const float* __restrict__ W_hh) {
    int i = blockIdx.x * blockDim.x + threadIdx.x;
    if (i >= 1536 * 512) return;
    float x = W_hh[i];
    fp16 h = __float2half_rn(x);
    g_WhhHi[i] = h;
    g_WhhLo[i] = __float2half_rn(x - __half2float(h));
}
__global__ void k_splitWoT(const float* __restrict__ Wo1) {
    int i = blockIdx.x * blockDim.x + threadIdx.x;   // over 512*256
    if (i >= 512 * 256) return;
    int k = i >> 8, n = i & 255;
    g_Wo1Hi[n * 512 + k] = __float2half_rn(Wo1[i]);
}
__global__ void k_splitW2T(const float* __restrict__ W2) {
    int i = blockIdx.x * blockDim.x + threadIdx.x;   // over 1024*512
    if (i >= 1024 * 512) return;
    int k = i >> 9, n = i & 511;
    float x = W2[i];
    fp16 h = __float2half_rn(x);
    g_W2Hi[n * 1024 + k] = h;
    g_W2Lo[n * 1024 + k] = __float2half_rn(x - __half2float(h));
}
__global__ void k_splitW1T(const float* __restrict__ W1) {
    int i = blockIdx.x * blockDim.x + threadIdx.x;   // over 1024*192
    if (i >= 1024 * 192) return;
    int n = i / 192, k = i % 192;
    float x = (k < 160) ? W1[(size_t)k * 1024 + n] : 0.f;
    fp16 h = __float2half_rn(x);
    g_W1Hi[i] = h;
    g_W1Lo[i] = __float2half_rn(x - __half2float(h));
}

// ============================ GRU step (mma.sync) ===========================
// fp16 2-term (state hi plane x weight hi+lo planes). SW128, K-chunk 64,
// double-buffered cp.async, 128KB smem, 512 threads. UNCHANGED from R11.
#define GRU_SMEM (128 * 1024)

__device__ __forceinline__ void gru_copy(uint32_t sb, int c, int b, int bM, int bJ,
                                         int tid, const fp16* hiIn) {
#pragma unroll
    for (int i = 0; i < 2; ++i) {            // A: 1024 segs of 16B
        int seg = tid + 512 * i, row = seg >> 3, s = seg & 7;
        const fp16* src = hiIn + (size_t)(bM * 128 + row) * 512 + c * 64 + s * 8;
        cpasync16(sb + b * 16384 + swz(row * 128 + s * 16), src);
    }
#pragma unroll
    for (int i = 0; i < 6; ++i) {            // B: 3072 segs of 16B
        int seg = tid + 512 * i;
        int hl = seg >= 1536 ? 1 : 0, rem = seg - hl * 1536, row = rem >> 3, s = rem & 7;
        int grow = (row >> 6) * 512 + bJ * 64 + (row & 63);
        const fp16* src = (hl ? g_WhhLo : g_WhhHi) + (size_t)grow * 512 + c * 64 + s * 8;
        cpasync16(sb + 32768 + b * 49152 + hl * 24576 + swz(row * 128 + s * 16), src);
    }
}

__global__ __launch_bounds__(512, 1) void k_gru_mma(
    const float* __restrict__ W_ih, const float* __restrict__ b_ih,
    const float* __restrict__ b_hh, int t)
{
    extern __shared__ char smem[];
    const fp16* hiIn  = (t & 1) ? g_hiB : g_hiA;
    const fp16* loIn  = (t & 1) ? g_loB : g_loA;
    fp16*       hiOut = (t & 1) ? g_hiA : g_hiB;
    fp16*       loOut = (t & 1) ? g_loA : g_loB;

    const int bJ = blockIdx.x, bM = blockIdx.y, tid = threadIdx.x;
    const int wid = tid >> 5, lane = tid & 31;
    const int mgrp = wid >> 2, ngrp = wid & 3;
    uint32_t sb = smem_u32(smem);

    float acc[3][2][2][4];
#pragma unroll
    for (int g = 0; g < 3; ++g)
#pragma unroll
        for (int mt = 0; mt < 2; ++mt)
#pragma unroll
            for (int nt = 0; nt < 2; ++nt)
#pragma unroll
                for (int c = 0; c < 4; ++c) acc[g][mt][nt][c] = 0.f;

    gru_copy(sb, 0, 0, bM, bJ, tid, hiIn);
    CP_COMMIT();

    for (int c = 0; c < 8; ++c) {
        int b = c & 1;
        if (c + 1 < 8) { gru_copy(sb, c + 1, b ^ 1, bM, bJ, tid, hiIn); CP_COMMIT(); CP_WAIT1(); }
        else CP_WAIT0();
        __syncthreads();
#pragma unroll
        for (int ks = 0; ks < 4; ++ks) {
            uint32_t aH[2][4], bH[3][4], bL[3][4];
#pragma unroll
            for (int mt = 0; mt < 2; ++mt) {
                int arow = mgrp * 32 + mt * 16 + (lane & 15);
                uint32_t off = swz(arow * 128 + ks * 32 + (lane >> 4) * 16);
                ldmx4(aH[mt], sb + b * 16384 + off);
            }
#pragma unroll
            for (int g = 0; g < 3; ++g) {
                int brow = g * 64 + ngrp * 16 + (lane & 7) + ((lane >> 4) & 1) * 8;
                uint32_t boff = swz(brow * 128 + ks * 32 + ((lane >> 3) & 1) * 16);
                ldmx4(bH[g], sb + 32768 + b * 49152 + boff);
                ldmx4(bL[g], sb + 32768 + b * 49152 + 24576 + boff);
            }
#pragma unroll
            for (int g = 0; g < 3; ++g)
#pragma unroll
                for (int mt = 0; mt < 2; ++mt)
#pragma unroll
                    for (int nt = 0; nt < 2; ++nt)
                        mma_fp16(acc[g][mt][nt], aH[mt], bH[g] + nt * 2);
#pragma unroll
            for (int g = 0; g < 3; ++g)
#pragma unroll
                for (int mt = 0; mt < 2; ++mt)
#pragma unroll
                    for (int nt = 0; nt < 2; ++nt)
                        mma_fp16(acc[g][mt][nt], aH[mt], bL[g] + nt * 2);
        }
        __syncthreads();
    }

    // ---- in-register gate epilogue ----
#pragma unroll
    for (int nt = 0; nt < 2; ++nt) {
        const int j = bJ * 64 + ngrp * 16 + nt * 8 + (lane & 3) * 2;
        float wih[3][2], bih[3][2], bhh[3][2];
#pragma unroll
        for (int g = 0; g < 3; ++g)
#pragma unroll
            for (int cc = 0; cc < 2; ++cc) {
                wih[g][cc] = W_ih[g * 512 + j + cc];
                bih[g][cc] = b_ih[g * 512 + j + cc];
                bhh[g][cc] = b_hh[g * 512 + j + cc];
            }
#pragma unroll
        for (int mt = 0; mt < 2; ++mt)
#pragma unroll
            for (int half = 0; half < 2; ++half) {
                int row = bM * 128 + mgrp * 32 + mt * 16 + (lane >> 2) + half * 8;
                float xi = g_x[row];
                __half2 h2 = *(const __half2*)(hiIn + (size_t)row * 512 + j);
                __half2 l2 = *(const __half2*)(loIn + (size_t)row * 512 + j);
                float hOld[2] = { __half2float(h2.x) + __half2float(l2.x),
                                  __half2float(h2.y) + __half2float(l2.y) };
                float hn[2];
#pragma unroll
                for (int cc = 0; cc < 2; ++cc) {
                    float ghr = acc[0][mt][nt][half * 2 + cc];
                    float ghz = acc[1][mt][nt][half * 2 + cc];
                    float ghn = acc[2][mt][nt][half * 2 + cc];
                    float rr = sig_(fmaf(xi, wih[0][cc], bih[0][cc]) + ghr + bhh[0][cc]);
                    float zz = sig_(fmaf(xi, wih[1][cc], bih[1][cc]) + ghz + bhh[1][cc]);
                    float nn = tanhf(fmaf(xi, wih[2][cc], bih[2][cc]) + rr * (ghn + bhh[2][cc]));
                    hn[cc] = (1.0f - zz) * nn + zz * hOld[cc];
                }
                fp16 h0 = __float2half_rn(hn[0]), h1 = __float2half_rn(hn[1]);
                __half2 hh; hh.x = h0; hh.y = h1;
                __half2 ll;
                ll.x = __float2half_rn(hn[0] - __half2float(h0));
                ll.y = __float2half_rn(hn[1] - __half2float(h1));
                *(__half2*)(hiOut + (size_t)row * 512 + j) = hh;
                *(__half2*)(loOut + (size_t)row * 512 + j) = ll;
            }
    }
}

// ============ fused output head: GEMM + LN + GELU + dot + write =============
// Block = 128 rows x ALL 256 cols, 512 threads (16 warps = 4 mgrp x 4 ngrp).
// Warp = 32 rows x 64 cols, 1-term fp16 (Wo1 hi plane). After GEMM, acc goes
// through a 135KB smem transpose; LN + GELU + Wo2-dot + out/g_x write in-kernel.
#define OH_SMEM (136 * 1024)

__device__ __forceinline__ void oh_copy(uint32_t sb, int c, int b, int bM,
                                        int tid, const fp16* hiIn) {
#pragma unroll
    for (int i = 0; i < 2; ++i) {            // A: 1024 segs
        int seg = tid + 512 * i, row = seg >> 3, s = seg & 7;
        const fp16* src = hiIn + (size_t)(bM * 128 + row) * 512 + c * 64 + s * 8;
        cpasync16(sb + b * 16384 + swz(row * 128 + s * 16), src);
    }
#pragma unroll
    for (int i = 0; i < 4; ++i) {            // B: 2048 segs (256 rows)
        int seg = tid + 512 * i, row = seg >> 3, s = seg & 7;
        const fp16* src = g_Wo1Hi + (size_t)row * 512 + c * 64 + s * 8;
        cpasync16(sb + 32768 + b * 32768 + swz(row * 128 + s * 16), src);
    }
}

__global__ __launch_bounds__(512, 1) void k_outhead(
    const float* __restrict__ bo1, const float* __restrict__ go,
    const float* __restrict__ beo, const float* __restrict__ Wo2,
    const float* __restrict__ bo2, float* __restrict__ out, int t)
{
    extern __shared__ char smem[];
    const fp16* hiIn = (t & 1) ? g_hiA : g_hiB;   // h_new from gru(t)
    const int bM = blockIdx.x, tid = threadIdx.x;
    const int wid = tid >> 5, lane = tid & 31;
    const int mgrp = wid >> 2, ngrp = wid & 3;
    uint32_t sb = smem_u32(smem);

    float acc[2][8][4];   // mt x n8-tile x quad
#pragma unroll
    for (int mt = 0; mt < 2; ++mt)
#pragma unroll
        for (int n8 = 0; n8 < 8; ++n8)
#pragma unroll
            for (int c = 0; c < 4; ++c) acc[mt][n8][c] = 0.f;

    oh_copy(sb, 0, 0, bM, tid, hiIn);
    CP_COMMIT();

    for (int c = 0; c < 8; ++c) {
        int b = c & 1;
        if (c + 1 < 8) { oh_copy(sb, c + 1, b ^ 1, bM, tid, hiIn); CP_COMMIT(); CP_WAIT1(); }
        else CP_WAIT0();
        __syncthreads();
#pragma unroll
        for (int ks = 0; ks < 4; ++ks) {
            uint32_t aH[2][4];
#pragma unroll
            for (int mt = 0; mt < 2; ++mt) {
                int arow = mgrp * 32 + mt * 16 + (lane & 15);
                uint32_t off = swz(arow * 128 + ks * 32 + (lane >> 4) * 16);
                ldmx4(aH[mt], sb + b * 16384 + off);
            }
#pragma unroll
            for (int g16 = 0; g16 < 4; ++g16) {    // 4 n16 groups = 64 cols
                int brow = ngrp * 64 + g16 * 16 + (lane & 7) + ((lane >> 4) & 1) * 8;
                uint32_t boff = swz(brow * 128 + ks * 32 + ((lane >> 3) & 1) * 16);
                uint32_t bB[4];
                ldmx4(bB, sb + 32768 + b * 32768 + boff);
#pragma unroll
                for (int mt = 0; mt < 2; ++mt)
#pragma unroll
                    for (int nt = 0; nt < 2; ++nt)
                        mma_fp16(acc[mt][g16 * 2 + nt], aH[mt], bB + nt * 2);
            }
        }
        __syncthreads();
    }

    // ---- epilogue: acc -> smem transpose ----
    float* sm = (float*)smem;                  // [128][264]
#pragma unroll
    for (int mt = 0; mt < 2; ++mt)
#pragma unroll
        for (int n8 = 0; n8 < 8; ++n8)
#pragma unroll
            for (int half = 0; half < 2; ++half) {
                int row_l = mgrp * 32 + mt * 16 + (lane >> 2) + half * 8;
                int col = ngrp * 64 + n8 * 8 + (lane & 3) * 2;
                *(float2*)&sm[row_l * 264 + col] =
                    make_float2(acc[mt][n8][half * 2], acc[mt][n8][half * 2 + 1]);
            }
    __syncthreads();

    // ---- LN + GELU + dot(Wo2): warp handles 8 rows, lane covers 8 cols ----
    const int j0 = lane * 8;
    float bo1v[8], gov[8], beov[8], wo2v[8];
#pragma unroll
    for (int c = 0; c < 8; ++c) {
        bo1v[c] = bo1[j0 + c]; gov[c] = go[j0 + c];
        beov[c] = beo[j0 + c]; wo2v[c] = Wo2[j0 + c];
    }
    const float bo2v = bo2[0];
#pragma unroll
    for (int r = 0; r < 8; ++r) {
        int row_l = wid * 8 + r;
        float v[8];
#pragma unroll
        for (int c = 0; c < 8; ++c) v[c] = sm[row_l * 264 + j0 + c];
        float s = 0.f;
#pragma unroll
        for (int c = 0; c < 8; ++c) { v[c] += bo1v[c]; s += v[c]; }
#pragma unroll
        for (int m = 16; m >= 1; m >>= 1) s += __shfl_xor_sync(~0u, s, m);
        float mean = s * (1.0f / 256.0f);
        float q = 0.f;
#pragma unroll
        for (int c = 0; c < 8; ++c) { float d = v[c] - mean; q += d * d; }
#pragma unroll
        for (int m = 16; m >= 1; m >>= 1) q += __shfl_xor_sync(~0u, q, m);
        float rstd = rsqrtf(q * (1.0f / 256.0f) + 1e-5f);
        float y = 0.f;
#pragma unroll
        for (int c = 0; c < 8; ++c) {
            float ln = (v[c] - mean) * rstd * gov[c] + beov[c];
            y += gelu_(ln) * wo2v[c];
        }
#pragma unroll
        for (int m = 16; m >= 1; m >>= 1) y += __shfl_xor_sync(~0u, y, m);
        if (lane == 0) {
            float yy = y + bo2v;
            int row = bM * 128 + row_l;
            out[(size_t)row * 20 + t] = yy;
            g_x[row] = yy;
        }
    }
}

// ======== generic 128-row x 64-col fp16 2-term mma GEMM (init only) =========
#define MMA64_SMEM (64 * 1024)

__device__ __forceinline__ void mma64_copy(uint32_t sb, int c, int b, int bM, int bJ,
                                           int tid, const fp16* aHi,
                                           const fp16* bHi, const fp16* bLo, int K) {
#pragma unroll
    for (int i = 0; i < 4; ++i) {            // A: 1024 segs
        int seg = tid + 256 * i, row = seg >> 3, s = seg & 7;
        const fp16* src = aHi + (size_t)(bM * 128 + row) * K + c * 64 + s * 8;
        cpasync16(sb + b * 16384 + swz(row * 128 + s * 16), src);
    }
#pragma unroll
    for (int i = 0; i < 4; ++i) {            // B: 1024 segs (2 planes x 64 rows)
        int seg = tid + 256 * i, hl = seg >> 9, rem = seg & 511, row = rem >> 3, s = rem & 7;
        const fp16* src = (hl ? bLo : bHi) + (size_t)(bJ * 64 + row) * K + c * 64 + s * 8;
        cpasync16(sb + 32768 + b * 16384 + hl * 8192 + swz(row * 128 + s * 16), src);
    }
}

template <int KDIM, int MODE>   // MODE 1: tanh(acc+bias)->g_hiA/g_loA; MODE 2: acc+bias->g_u
__global__ __launch_bounds__(256, 2) void k_mma64(
    const fp16* __restrict__ aHi,
    const fp16* __restrict__ bHi, const fp16* __restrict__ bLo,
    const float* __restrict__ bias)
{
    extern __shared__ char smem[];
    const int bJ = blockIdx.x, bM = blockIdx.y, tid = threadIdx.x;
    const int wid = tid >> 5, lane = tid & 31;
    const int mgrp = wid >> 2, ngrp = wid & 3;
    uint32_t sb = smem_u32(smem);
    const int NCH = KDIM / 64;

    float acc[4][2][4];
#pragma unroll
    for (int mt = 0; mt < 4; ++mt)
#pragma unroll
        for (int nt = 0; nt < 2; ++nt)
#pragma unroll
            for (int c = 0; c < 4; ++c) acc[mt][nt][c] = 0.f;

    mma64_copy(sb, 0, 0, bM, bJ, tid, aHi, bHi, bLo, KDIM);
    CP_COMMIT();

    for (int c = 0; c < NCH; ++c) {
        int b = c & 1;
        if (c + 1 < NCH) { mma64_copy(sb, c + 1, b ^ 1, bM, bJ, tid, aHi, bHi, bLo, KDIM);
                           CP_COMMIT(); CP_WAIT1(); }
        else CP_WAIT0();
        __syncthreads();
#pragma unroll
        for (int ks = 0; ks < 4; ++ks) {
            uint32_t aH[4][4], bH[4], bL[4];
#pragma unroll
            for (int mt = 0; mt < 4; ++mt) {
                int arow = mgrp * 64 + mt * 16 + (lane & 15);
                uint32_t off = swz(arow * 128 + ks * 32 + (lane >> 4) * 16);
                ldmx4(aH[mt], sb + b * 16384 + off);
            }
            int brow = ngrp * 16 + (lane & 7) + ((lane >> 4) & 1) * 8;
            uint32_t boff = swz(brow * 128 + ks * 32 + ((lane >> 3) & 1) * 16);
            ldmx4(bH, sb + 32768 + b * 16384 + boff);
            ldmx4(bL, sb + 32768 + b * 16384 + 8192 + boff);
#pragma unroll
            for (int mt = 0; mt < 4; ++mt)
#pragma unroll
                for (int nt = 0; nt < 2; ++nt)
                    mma_fp16(acc[mt][nt], aH[mt], bH + nt * 2);
#pragma unroll
            for (int mt = 0; mt < 4; ++mt)
#pragma unroll
                for (int nt = 0; nt < 2; ++nt)
                    mma_fp16(acc[mt][nt], aH[mt], bL + nt * 2);
        }
        __syncthreads();
    }

#pragma unroll
    for (int nt = 0; nt < 2; ++nt) {
        const int n = bJ * 64 + ngrp * 16 + nt * 8 + (lane & 3) * 2;
#pragma unroll
        for (int mt = 0; mt < 4; ++mt)
#pragma unroll
            for (int half = 0; half < 2; ++half) {
                int row = bM * 128 + mgrp * 64 + mt * 16 + (lane >> 2) + half * 8;
                if (MODE == 1) {
                    float hn0 = tanhf(acc[mt][nt][half * 2]     + bias[n]);
                    float hn1 = tanhf(acc[mt][nt][half * 2 + 1] + bias[n + 1]);
                    fp16 h0 = __float2half_rn(hn0), h1 = __float2half_rn(hn1);
                    __half2 hh; hh.x = h0; hh.y = h1;
                    __half2 ll;
                    ll.x = __float2half_rn(hn0 - __half2float(h0));
                    ll.y = __float2half_rn(hn1 - __half2float(h1));
                    *(__half2*)(g_hiA + (size_t)row * 512 + n) = hh;
                    *(__half2*)(g_loA + (size_t)row * 512 + n) = ll;
                } else {
                    *(float2*)(g_u + (size_t)row * 1024 + n) =
                        make_float2(acc[mt][nt][half * 2] + bias[n],
                                    acc[mt][nt][half * 2 + 1] + bias[n + 1]);
                }
            }
    }
}

// ================================== host ====================================
extern "C" void kernel_launch(void* const* d_in, const int* in_sizes, int n_in,
                              void* d_out, int out_size) {
    const float* z_q   = (const float*)d_in[0];
    const float* f_pr  = (const float*)d_in[1];
    const float* W1    = (const float*)d_in[2];
    const float* b1    = (const float*)d_in[3];
    const float* g1    = (const float*)d_in[4];
    const float* be1   = (const float*)d_in[5];
    const float* W2    = (const float*)d_in[6];
    const float* b2    = (const float*)d_in[7];
    const float* start = (const float*)d_in[8];
    const float* W_ih  = (const float*)d_in[9];
    const float* W_hh  = (const float*)d_in[10];
    const float* b_ih  = (const float*)d_in[11];
    const float* b_hh  = (const float*)d_in[12];
    const float* Wo1   = (const float*)d_in[13];
    const float* bo1   = (const float*)d_in[14];
    const float* go    = (const float*)d_in[15];
    const float* beo   = (const float*)d_in[16];
    const float* Wo2   = (const float*)d_in[17];
    const float* bo2   = (const float*)d_in[18];
    float* out = (float*)d_out;

    cudaFuncSetAttribute(k_gru_mma, cudaFuncAttributeMaxDynamicSharedMemorySize, GRU_SMEM);
    cudaFuncSetAttribute(k_outhead, cudaFuncAttributeMaxDynamicSharedMemorySize, OH_SMEM);
    cudaFuncSetAttribute(k_mma64<1024, 1>, cudaFuncAttributeMaxDynamicSharedMemorySize, MMA64_SMEM);
    cudaFuncSetAttribute(k_mma64<192, 2>, cudaFuncAttributeMaxDynamicSharedMemorySize, MMA64_SMEM);

    fp16 *cHiP, *uHiP, *w2HiP, *w2LoP, *w1HiP, *w1LoP;
    cudaGetSymbolAddress((void**)&cHiP, g_cHi);
    cudaGetSymbolAddress((void**)&uHiP, g_uHi);
    cudaGetSymbolAddress((void**)&w2HiP, g_W2Hi);
    cudaGetSymbolAddress((void**)&w2LoP, g_W2Lo);
    cudaGetSymbolAddress((void**)&w1HiP, g_W1Hi);
    cudaGetSymbolAddress((void**)&w1LoP, g_W1Lo);

    // weight prep
    k_splitWhh<<<(1536 * 512 + 255) / 256, 256>>>(W_hh);
    k_splitWoT<<<(512 * 256 + 255) / 256, 256>>>(Wo1);
    k_splitW2T<<<(1024 * 512 + 255) / 256, 256>>>(W2);
    k_splitW1T<<<(1024 * 192 + 255) / 256, 256>>>(W1);

    // init MLP
    k_prep<<<(int)(((size_t)NR * 192 + 255) / 256), 256>>>(z_q, f_pr);
    k_mma64<192, 2><<<dim3(16, NR / 128), 256, MMA64_SMEM>>>(cHiP, w1HiP, w1LoP, b1);
    k_lngelu<<<NR, 256>>>(g1, be1);
    k_mma64<1024, 1><<<dim3(8, NR / 128), 256, MMA64_SMEM>>>(uHiP, w2HiP, w2LoP, b2);
    k_setx<<<NR / 256, 256>>>(start);

    // recurrence
    for (int t = 0; t < 20; ++t) {
        k_gru_mma<<<dim3(8, NR / 128), 512, GRU_SMEM>>>(W_ih, b_ih, b_hh, t);
        k_outhead<<<NR / 128, 512, OH_SMEM>>>(bo1, go, beo, Wo2, bo2, out, t);
    }
}

// round 13
// speedup vs baseline: 1.8931x; 1.3373x over previous
#include <cuda_runtime.h>
#include <cuda_fp16.h>
#include <cstdint>

#define NR 65536
typedef __half fp16;

// ----------------------------- device scratch ------------------------------
__device__ float g_u[(size_t)NR * 1024];
__device__ fp16  g_cHi[(size_t)NR * 192];    // concat(z,f) padded to K=192
__device__ fp16  g_uHi[(size_t)NR * 1024];
__device__ fp16  g_hiA[(size_t)NR * 512];
__device__ fp16  g_loA[(size_t)NR * 512];
__device__ fp16  g_hiB[(size_t)NR * 512];
__device__ fp16  g_loB[(size_t)NR * 512];
__device__ float g_x[NR];
__device__ fp16  g_WhhHi[1536 * 512];
__device__ fp16  g_Wo1Hi[256 * 512];     // transposed [N=256, K=512], hi only
__device__ fp16  g_W2Hi[512 * 1024];     // transposed [N=512, K=1024]
__device__ fp16  g_W2Lo[512 * 1024];
__device__ fp16  g_W1Hi[1024 * 192];     // transposed+padded [N=1024, K=192]
__device__ fp16  g_W1Lo[1024 * 192];

// ----------------------------- small helpers -------------------------------
__device__ __forceinline__ float sig_(float x) { return 1.0f / (1.0f + expf(-x)); }
__device__ __forceinline__ float gelu_(float x) {
    return 0.5f * x * (1.0f + erff(x * 0.70710678f));
}
__device__ __forceinline__ uint32_t smem_u32(const void* p) {
    uint32_t a;
    asm("{ .reg .u64 t; cvta.to.shared.u64 t, %1; cvt.u32.u64 %0, t; }" : "=r"(a) : "l"(p));
    return a;
}
__device__ __forceinline__ uint32_t swz(uint32_t off) { return off ^ ((off >> 3) & 0x70); }

__device__ __forceinline__ void cpasync16(uint32_t saddr, const void* gptr) {
    asm volatile("{ .reg .u64 g; cvta.to.global.u64 g, %1; "
                 "cp.async.cg.shared.global [%0], [g], 16; }"
                 :: "r"(saddr), "l"(gptr) : "memory");
}
#define CP_COMMIT() asm volatile("cp.async.commit_group;" ::: "memory")
#define CP_WAIT1()  asm volatile("cp.async.wait_group 1;" ::: "memory")
#define CP_WAIT0()  asm volatile("cp.async.wait_group 0;" ::: "memory")

__device__ __forceinline__ void ldmx4(uint32_t* r, uint32_t addr) {
    asm volatile("ldmatrix.sync.aligned.m8n8.x4.shared.b16 {%0,%1,%2,%3}, [%4];"
        : "=r"(r[0]), "=r"(r[1]), "=r"(r[2]), "=r"(r[3]) : "r"(addr));
}
__device__ __forceinline__ void mma_fp16(float* d, const uint32_t* a, const uint32_t* b) {
    asm volatile("mma.sync.aligned.m16n8k16.row.col.f32.f16.f16.f32 "
        "{%0,%1,%2,%3}, {%4,%5,%6,%7}, {%8,%9}, {%0,%1,%2,%3};"
        : "+f"(d[0]), "+f"(d[1]), "+f"(d[2]), "+f"(d[3])
        : "r"(a[0]), "r"(a[1]), "r"(a[2]), "r"(a[3]), "r"(b[0]), "r"(b[1]));
}

// =========================== init-path kernels =============================
__global__ void k_prep(const float* __restrict__ z, const float* __restrict__ f) {
    size_t i = (size_t)blockIdx.x * blockDim.x + threadIdx.x;
    if (i >= (size_t)NR * 192) return;
    int row = (int)(i / 192), col = (int)(i % 192);
    float x = (col < 128) ? z[(size_t)row * 128 + col]
            : (col < 160) ? f[(size_t)row * 32 + col - 128] : 0.f;
    g_cHi[i] = __float2half_rn(x);
}

__global__ __launch_bounds__(256) void k_lngelu(
    const float* __restrict__ g1, const float* __restrict__ be1)
{
    const size_t row = blockIdx.x;
    const int tid = threadIdx.x, lane = tid & 31, w = tid >> 5;
    const float* up = g_u + row * 1024 + tid * 4;
    float4 v = *(const float4*)up;
    __shared__ float red[8];
    float s = v.x + v.y + v.z + v.w;
#pragma unroll
    for (int m = 16; m >= 1; m >>= 1) s += __shfl_xor_sync(~0u, s, m);
    if (lane == 0) red[w] = s;
    __syncthreads();
    float tot = 0.f;
#pragma unroll
    for (int i = 0; i < 8; ++i) tot += red[i];
    const float mean = tot * (1.0f / 1024.0f);
    float dx = v.x - mean, dy = v.y - mean, dz = v.z - mean, dw = v.w - mean;
    float q = dx * dx + dy * dy + dz * dz + dw * dw;
#pragma unroll
    for (int m = 16; m >= 1; m >>= 1) q += __shfl_xor_sync(~0u, q, m);
    __syncthreads();
    if (lane == 0) red[w] = q;
    __syncthreads();
    float qt = 0.f;
#pragma unroll
    for (int i = 0; i < 8; ++i) qt += red[i];
    const float rstd = rsqrtf(qt * (1.0f / 1024.0f) + 1e-5f);
    const int j = tid * 4;
    float4 g4 = *(const float4*)&g1[j];
    float4 b4 = *(const float4*)&be1[j];
    __align__(8) fp16 hb[4];
    hb[0] = __float2half_rn(gelu_(dx * rstd * g4.x + b4.x));
    hb[1] = __float2half_rn(gelu_(dy * rstd * g4.y + b4.y));
    hb[2] = __float2half_rn(gelu_(dz * rstd * g4.z + b4.z));
    hb[3] = __float2half_rn(gelu_(dw * rstd * g4.w + b4.w));
    *(uint2*)(g_uHi + row * 1024 + j) = *(uint2*)hb;
}

__global__ void k_setx(const float* __restrict__ st) {
    int i = blockIdx.x * blockDim.x + threadIdx.x;
    if (i < NR) g_x[i] = st[0];
}

// -------- weight prep --------
__global__ void k_cvtWhh(const float* __restrict__ W_hh) {
    int i = blockIdx.x * blockDim.x + threadIdx.x;
    if (i >= 1536 * 512) return;
    g_WhhHi[i] = __float2half_rn(W_hh[i]);
}
__global__ void k_splitWoT(const float* __restrict__ Wo1) {
    int i = blockIdx.x * blockDim.x + threadIdx.x;   // over 512*256
    if (i >= 512 * 256) return;
    int k = i >> 8, n = i & 255;
    g_Wo1Hi[n * 512 + k] = __float2half_rn(Wo1[i]);
}
__global__ void k_splitW2T(const float* __restrict__ W2) {
    int i = blockIdx.x * blockDim.x + threadIdx.x;   // over 1024*512
    if (i >= 1024 * 512) return;
    int k = i >> 9, n = i & 511;
    float x = W2[i];
    fp16 h = __float2half_rn(x);
    g_W2Hi[n * 1024 + k] = h;
    g_W2Lo[n * 1024 + k] = __float2half_rn(x - __half2float(h));
}
__global__ void k_splitW1T(const float* __restrict__ W1) {
    int i = blockIdx.x * blockDim.x + threadIdx.x;   // over 1024*192
    if (i >= 1024 * 192) return;
    int n = i / 192, k = i % 192;
    float x = (k < 160) ? W1[(size_t)k * 1024 + n] : 0.f;
    fp16 h = __float2half_rn(x);
    g_W1Hi[i] = h;
    g_W1Lo[i] = __float2half_rn(x - __half2float(h));
}

// ============================ GRU step (mma.sync) ===========================
// 1-term fp16: gh = h_hi @ WhhHi^T (W lo-plane dropped this round).
// SW128, K-chunk 64, double-buffered cp.async, 80KB smem, 512 threads.
// SMEM: A[buf] @ b*16384 (128 rows x 128B); B[buf] @ 32768 + b*24576 (192 rows).
#define GRU_SMEM (80 * 1024)

__device__ __forceinline__ void gru_copy(uint32_t sb, int c, int b, int bM, int bJ,
                                         int tid, const fp16* hiIn) {
#pragma unroll
    for (int i = 0; i < 2; ++i) {            // A: 1024 segs of 16B
        int seg = tid + 512 * i, row = seg >> 3, s = seg & 7;
        const fp16* src = hiIn + (size_t)(bM * 128 + row) * 512 + c * 64 + s * 8;
        cpasync16(sb + b * 16384 + swz(row * 128 + s * 16), src);
    }
#pragma unroll
    for (int i = 0; i < 3; ++i) {            // B: 1536 segs of 16B (192 rows)
        int seg = tid + 512 * i, row = seg >> 3, s = seg & 7;
        int grow = (row >> 6) * 512 + bJ * 64 + (row & 63);
        const fp16* src = g_WhhHi + (size_t)grow * 512 + c * 64 + s * 8;
        cpasync16(sb + 32768 + b * 24576 + swz(row * 128 + s * 16), src);
    }
}

__global__ __launch_bounds__(512, 1) void k_gru_mma(
    const float* __restrict__ W_ih, const float* __restrict__ b_ih,
    const float* __restrict__ b_hh, int t)
{
    extern __shared__ char smem[];
    const fp16* hiIn  = (t & 1) ? g_hiB : g_hiA;
    const fp16* loIn  = (t & 1) ? g_loB : g_loA;
    fp16*       hiOut = (t & 1) ? g_hiA : g_hiB;
    fp16*       loOut = (t & 1) ? g_loA : g_loB;

    const int bJ = blockIdx.x, bM = blockIdx.y, tid = threadIdx.x;
    const int wid = tid >> 5, lane = tid & 31;
    const int mgrp = wid >> 2, ngrp = wid & 3;
    uint32_t sb = smem_u32(smem);

    float acc[3][2][2][4];
#pragma unroll
    for (int g = 0; g < 3; ++g)
#pragma unroll
        for (int mt = 0; mt < 2; ++mt)
#pragma unroll
            for (int nt = 0; nt < 2; ++nt)
#pragma unroll
                for (int c = 0; c < 4; ++c) acc[g][mt][nt][c] = 0.f;

    gru_copy(sb, 0, 0, bM, bJ, tid, hiIn);
    CP_COMMIT();

    for (int c = 0; c < 8; ++c) {
        int b = c & 1;
        if (c + 1 < 8) { gru_copy(sb, c + 1, b ^ 1, bM, bJ, tid, hiIn); CP_COMMIT(); CP_WAIT1(); }
        else CP_WAIT0();
        __syncthreads();
#pragma unroll
        for (int ks = 0; ks < 4; ++ks) {
            uint32_t aH[2][4], bH[3][4];
#pragma unroll
            for (int mt = 0; mt < 2; ++mt) {
                int arow = mgrp * 32 + mt * 16 + (lane & 15);
                uint32_t off = swz(arow * 128 + ks * 32 + (lane >> 4) * 16);
                ldmx4(aH[mt], sb + b * 16384 + off);
            }
#pragma unroll
            for (int g = 0; g < 3; ++g) {
                int brow = g * 64 + ngrp * 16 + (lane & 7) + ((lane >> 4) & 1) * 8;
                uint32_t boff = swz(brow * 128 + ks * 32 + ((lane >> 3) & 1) * 16);
                ldmx4(bH[g], sb + 32768 + b * 24576 + boff);
            }
#pragma unroll
            for (int g = 0; g < 3; ++g)
#pragma unroll
                for (int mt = 0; mt < 2; ++mt)
#pragma unroll
                    for (int nt = 0; nt < 2; ++nt)
                        mma_fp16(acc[g][mt][nt], aH[mt], bH[g] + nt * 2);
        }
        __syncthreads();
    }

    // ---- in-register gate epilogue (h_old reconstructed from hi/lo) ----
#pragma unroll
    for (int nt = 0; nt < 2; ++nt) {
        const int j = bJ * 64 + ngrp * 16 + nt * 8 + (lane & 3) * 2;
        float wih[3][2], bih[3][2], bhh[3][2];
#pragma unroll
        for (int g = 0; g < 3; ++g)
#pragma unroll
            for (int cc = 0; cc < 2; ++cc) {
                wih[g][cc] = W_ih[g * 512 + j + cc];
                bih[g][cc] = b_ih[g * 512 + j + cc];
                bhh[g][cc] = b_hh[g * 512 + j + cc];
            }
#pragma unroll
        for (int mt = 0; mt < 2; ++mt)
#pragma unroll
            for (int half = 0; half < 2; ++half) {
                int row = bM * 128 + mgrp * 32 + mt * 16 + (lane >> 2) + half * 8;
                float xi = g_x[row];
                __half2 h2 = *(const __half2*)(hiIn + (size_t)row * 512 + j);
                __half2 l2 = *(const __half2*)(loIn + (size_t)row * 512 + j);
                float hOld[2] = { __half2float(h2.x) + __half2float(l2.x),
                                  __half2float(h2.y) + __half2float(l2.y) };
                float hn[2];
#pragma unroll
                for (int cc = 0; cc < 2; ++cc) {
                    float ghr = acc[0][mt][nt][half * 2 + cc];
                    float ghz = acc[1][mt][nt][half * 2 + cc];
                    float ghn = acc[2][mt][nt][half * 2 + cc];
                    float rr = sig_(fmaf(xi, wih[0][cc], bih[0][cc]) + ghr + bhh[0][cc]);
                    float zz = sig_(fmaf(xi, wih[1][cc], bih[1][cc]) + ghz + bhh[1][cc]);
                    float nn = tanhf(fmaf(xi, wih[2][cc], bih[2][cc]) + rr * (ghn + bhh[2][cc]));
                    hn[cc] = (1.0f - zz) * nn + zz * hOld[cc];
                }
                fp16 h0 = __float2half_rn(hn[0]), h1 = __float2half_rn(hn[1]);
                __half2 hh; hh.x = h0; hh.y = h1;
                __half2 ll;
                ll.x = __float2half_rn(hn[0] - __half2float(h0));
                ll.y = __float2half_rn(hn[1] - __half2float(h1));
                *(__half2*)(hiOut + (size_t)row * 512 + j) = hh;
                *(__half2*)(loOut + (size_t)row * 512 + j) = ll;
            }
    }
}

// ============ fused output head: GEMM + LN + GELU + dot + write =============
// Block = 128 rows x ALL 256 cols, 512 threads. UNCHANGED from R12.
#define OH_SMEM (136 * 1024)

__device__ __forceinline__ void oh_copy(uint32_t sb, int c, int b, int bM,
                                        int tid, const fp16* hiIn) {
#pragma unroll
    for (int i = 0; i < 2; ++i) {            // A: 1024 segs
        int seg = tid + 512 * i, row = seg >> 3, s = seg & 7;
        const fp16* src = hiIn + (size_t)(bM * 128 + row) * 512 + c * 64 + s * 8;
        cpasync16(sb + b * 16384 + swz(row * 128 + s * 16), src);
    }
#pragma unroll
    for (int i = 0; i < 4; ++i) {            // B: 2048 segs (256 rows)
        int seg = tid + 512 * i, row = seg >> 3, s = seg & 7;
        const fp16* src = g_Wo1Hi + (size_t)row * 512 + c * 64 + s * 8;
        cpasync16(sb + 32768 + b * 32768 + swz(row * 128 + s * 16), src);
    }
}

__global__ __launch_bounds__(512, 1) void k_outhead(
    const float* __restrict__ bo1, const float* __restrict__ go,
    const float* __restrict__ beo, const float* __restrict__ Wo2,
    const float* __restrict__ bo2, float* __restrict__ out, int t)
{
    extern __shared__ char smem[];
    const fp16* hiIn = (t & 1) ? g_hiA : g_hiB;   // h_new from gru(t)
    const int bM = blockIdx.x, tid = threadIdx.x;
    const int wid = tid >> 5, lane = tid & 31;
    const int mgrp = wid >> 2, ngrp = wid & 3;
    uint32_t sb = smem_u32(smem);

    float acc[2][8][4];
#pragma unroll
    for (int mt = 0; mt < 2; ++mt)
#pragma unroll
        for (int n8 = 0; n8 < 8; ++n8)
#pragma unroll
            for (int c = 0; c < 4; ++c) acc[mt][n8][c] = 0.f;

    oh_copy(sb, 0, 0, bM, tid, hiIn);
    CP_COMMIT();

    for (int c = 0; c < 8; ++c) {
        int b = c & 1;
        if (c + 1 < 8) { oh_copy(sb, c + 1, b ^ 1, bM, tid, hiIn); CP_COMMIT(); CP_WAIT1(); }
        else CP_WAIT0();
        __syncthreads();
#pragma unroll
        for (int ks = 0; ks < 4; ++ks) {
            uint32_t aH[2][4];
#pragma unroll
            for (int mt = 0; mt < 2; ++mt) {
                int arow = mgrp * 32 + mt * 16 + (lane & 15);
                uint32_t off = swz(arow * 128 + ks * 32 + (lane >> 4) * 16);
                ldmx4(aH[mt], sb + b * 16384 + off);
            }
#pragma unroll
            for (int g16 = 0; g16 < 4; ++g16) {
                int brow = ngrp * 64 + g16 * 16 + (lane & 7) + ((lane >> 4) & 1) * 8;
                uint32_t boff = swz(brow * 128 + ks * 32 + ((lane >> 3) & 1) * 16);
                uint32_t bB[4];
                ldmx4(bB, sb + 32768 + b * 32768 + boff);
#pragma unroll
                for (int mt = 0; mt < 2; ++mt)
#pragma unroll
                    for (int nt = 0; nt < 2; ++nt)
                        mma_fp16(acc[mt][g16 * 2 + nt], aH[mt], bB + nt * 2);
            }
        }
        __syncthreads();
    }

    float* sm = (float*)smem;                  // [128][264]
#pragma unroll
    for (int mt = 0; mt < 2; ++mt)
#pragma unroll
        for (int n8 = 0; n8 < 8; ++n8)
#pragma unroll
            for (int half = 0; half < 2; ++half) {
                int row_l = mgrp * 32 + mt * 16 + (lane >> 2) + half * 8;
                int col = ngrp * 64 + n8 * 8 + (lane & 3) * 2;
                *(float2*)&sm[row_l * 264 + col] =
                    make_float2(acc[mt][n8][half * 2], acc[mt][n8][half * 2 + 1]);
            }
    __syncthreads();

    const int j0 = lane * 8;
    float bo1v[8], gov[8], beov[8], wo2v[8];
#pragma unroll
    for (int c = 0; c < 8; ++c) {
        bo1v[c] = bo1[j0 + c]; gov[c] = go[j0 + c];
        beov[c] = beo[j0 + c]; wo2v[c] = Wo2[j0 + c];
    }
    const float bo2v = bo2[0];
#pragma unroll
    for (int r = 0; r < 8; ++r) {
        int row_l = wid * 8 + r;
        float v[8];
#pragma unroll
        for (int c = 0; c < 8; ++c) v[c] = sm[row_l * 264 + j0 + c];
        float s = 0.f;
#pragma unroll
        for (int c = 0; c < 8; ++c) { v[c] += bo1v[c]; s += v[c]; }
#pragma unroll
        for (int m = 16; m >= 1; m >>= 1) s += __shfl_xor_sync(~0u, s, m);
        float mean = s * (1.0f / 256.0f);
        float q = 0.f;
#pragma unroll
        for (int c = 0; c < 8; ++c) { float d = v[c] - mean; q += d * d; }
#pragma unroll
        for (int m = 16; m >= 1; m >>= 1) q += __shfl_xor_sync(~0u, q, m);
        float rstd = rsqrtf(q * (1.0f / 256.0f) + 1e-5f);
        float y = 0.f;
#pragma unroll
        for (int c = 0; c < 8; ++c) {
            float ln = (v[c] - mean) * rstd * gov[c] + beov[c];
            y += gelu_(ln) * wo2v[c];
        }
#pragma unroll
        for (int m = 16; m >= 1; m >>= 1) y += __shfl_xor_sync(~0u, y, m);
        if (lane == 0) {
            float yy = y + bo2v;
            int row = bM * 128 + row_l;
            out[(size_t)row * 20 + t] = yy;
            g_x[row] = yy;
        }
    }
}

// ======== generic 128-row x 64-col fp16 2-term mma GEMM (init only) =========
#define MMA64_SMEM (64 * 1024)

__device__ __forceinline__ void mma64_copy(uint32_t sb, int c, int b, int bM, int bJ,
                                           int tid, const fp16* aHi,
                                           const fp16* bHi, const fp16* bLo, int K) {
#pragma unroll
    for (int i = 0; i < 4; ++i) {
        int seg = tid + 256 * i, row = seg >> 3, s = seg & 7;
        const fp16* src = aHi + (size_t)(bM * 128 + row) * K + c * 64 + s * 8;
        cpasync16(sb + b * 16384 + swz(row * 128 + s * 16), src);
    }
#pragma unroll
    for (int i = 0; i < 4; ++i) {
        int seg = tid + 256 * i, hl = seg >> 9, rem = seg & 511, row = rem >> 3, s = rem & 7;
        const fp16* src = (hl ? bLo : bHi) + (size_t)(bJ * 64 + row) * K + c * 64 + s * 8;
        cpasync16(sb + 32768 + b * 16384 + hl * 8192 + swz(row * 128 + s * 16), src);
    }
}

template <int KDIM, int MODE>   // MODE 1: tanh(acc+bias)->g_hiA/g_loA; MODE 2: acc+bias->g_u
__global__ __launch_bounds__(256, 2) void k_mma64(
    const fp16* __restrict__ aHi,
    const fp16* __restrict__ bHi, const fp16* __restrict__ bLo,
    const float* __restrict__ bias)
{
    extern __shared__ char smem[];
    const int bJ = blockIdx.x, bM = blockIdx.y, tid = threadIdx.x;
    const int wid = tid >> 5, lane = tid & 31;
    const int mgrp = wid >> 2, ngrp = wid & 3;
    uint32_t sb = smem_u32(smem);
    const int NCH = KDIM / 64;

    float acc[4][2][4];
#pragma unroll
    for (int mt = 0; mt < 4; ++mt)
#pragma unroll
        for (int nt = 0; nt < 2; ++nt)
#pragma unroll
            for (int c = 0; c < 4; ++c) acc[mt][nt][c] = 0.f;

    mma64_copy(sb, 0, 0, bM, bJ, tid, aHi, bHi, bLo, KDIM);
    CP_COMMIT();

    for (int c = 0; c < NCH; ++c) {
        int b = c & 1;
        if (c + 1 < NCH) { mma64_copy(sb, c + 1, b ^ 1, bM, bJ, tid, aHi, bHi, bLo, KDIM);
                           CP_COMMIT(); CP_WAIT1(); }
        else CP_WAIT0();
        __syncthreads();
#pragma unroll
        for (int ks = 0; ks < 4; ++ks) {
            uint32_t aH[4][4], bH[4], bL[4];
#pragma unroll
            for (int mt = 0; mt < 4; ++mt) {
                int arow = mgrp * 64 + mt * 16 + (lane & 15);
                uint32_t off = swz(arow * 128 + ks * 32 + (lane >> 4) * 16);
                ldmx4(aH[mt], sb + b * 16384 + off);
            }
            int brow = ngrp * 16 + (lane & 7) + ((lane >> 4) & 1) * 8;
            uint32_t boff = swz(brow * 128 + ks * 32 + ((lane >> 3) & 1) * 16);
            ldmx4(bH, sb + 32768 + b * 16384 + boff);
            ldmx4(bL, sb + 32768 + b * 16384 + 8192 + boff);
#pragma unroll
            for (int mt = 0; mt < 4; ++mt)
#pragma unroll
                for (int nt = 0; nt < 2; ++nt)
                    mma_fp16(acc[mt][nt], aH[mt], bH + nt * 2);
#pragma unroll
            for (int mt = 0; mt < 4; ++mt)
#pragma unroll
                for (int nt = 0; nt < 2; ++nt)
                    mma_fp16(acc[mt][nt], aH[mt], bL + nt * 2);
        }
        __syncthreads();
    }

#pragma unroll
    for (int nt = 0; nt < 2; ++nt) {
        const int n = bJ * 64 + ngrp * 16 + nt * 8 + (lane & 3) * 2;
#pragma unroll
        for (int mt = 0; mt < 4; ++mt)
#pragma unroll
            for (int half = 0; half < 2; ++half) {
                int row = bM * 128 + mgrp * 64 + mt * 16 + (lane >> 2) + half * 8;
                if (MODE == 1) {
                    float hn0 = tanhf(acc[mt][nt][half * 2]     + bias[n]);
                    float hn1 = tanhf(acc[mt][nt][half * 2 + 1] + bias[n + 1]);
                    fp16 h0 = __float2half_rn(hn0), h1 = __float2half_rn(hn1);
                    __half2 hh; hh.x = h0; hh.y = h1;
                    __half2 ll;
                    ll.x = __float2half_rn(hn0 - __half2float(h0));
                    ll.y = __float2half_rn(hn1 - __half2float(h1));
                    *(__half2*)(g_hiA + (size_t)row * 512 + n) = hh;
                    *(__half2*)(g_loA + (size_t)row * 512 + n) = ll;
                } else {
                    *(float2*)(g_u + (size_t)row * 1024 + n) =
                        make_float2(acc[mt][nt][half * 2] + bias[n],
                                    acc[mt][nt][half * 2 + 1] + bias[n + 1]);
                }
            }
    }
}

// ================================== host ====================================
extern "C" void kernel_launch(void* const* d_in, const int* in_sizes, int n_in,
                              void* d_out, int out_size) {
    const float* z_q   = (const float*)d_in[0];
    const float* f_pr  = (const float*)d_in[1];
    const float* W1    = (const float*)d_in[2];
    const float* b1    = (const float*)d_in[3];
    const float* g1    = (const float*)d_in[4];
    const float* be1   = (const float*)d_in[5];
    const float* W2    = (const float*)d_in[6];
    const float* b2    = (const float*)d_in[7];
    const float* start = (const float*)d_in[8];
    const float* W_ih  = (const float*)d_in[9];
    const float* W_hh  = (const float*)d_in[10];
    const float* b_ih  = (const float*)d_in[11];
    const float* b_hh  = (const float*)d_in[12];
    const float* Wo1   = (const float*)d_in[13];
    const float* bo1   = (const float*)d_in[14];
    const float* go    = (const float*)d_in[15];
    const float* beo   = (const float*)d_in[16];
    const float* Wo2   = (const float*)d_in[17];
    const float* bo2   = (const float*)d_in[18];
    float* out = (float*)d_out;

    cudaFuncSetAttribute(k_gru_mma, cudaFuncAttributeMaxDynamicSharedMemorySize, GRU_SMEM);
    cudaFuncSetAttribute(k_outhead, cudaFuncAttributeMaxDynamicSharedMemorySize, OH_SMEM);
    cudaFuncSetAttribute(k_mma64<1024, 1>, cudaFuncAttributeMaxDynamicSharedMemorySize, MMA64_SMEM);
    cudaFuncSetAttribute(k_mma64<192, 2>, cudaFuncAttributeMaxDynamicSharedMemorySize, MMA64_SMEM);

    fp16 *cHiP, *uHiP, *w2HiP, *w2LoP, *w1HiP, *w1LoP;
    cudaGetSymbolAddress((void**)&cHiP, g_cHi);
    cudaGetSymbolAddress((void**)&uHiP, g_uHi);
    cudaGetSymbolAddress((void**)&w2HiP, g_W2Hi);
    cudaGetSymbolAddress((void**)&w2LoP, g_W2Lo);
    cudaGetSymbolAddress((void**)&w1HiP, g_W1Hi);
    cudaGetSymbolAddress((void**)&w1LoP, g_W1Lo);

    // weight prep
    k_cvtWhh<<<(1536 * 512 + 255) / 256, 256>>>(W_hh);
    k_splitWoT<<<(512 * 256 + 255) / 256, 256>>>(Wo1);
    k_splitW2T<<<(1024 * 512 + 255) / 256, 256>>>(W2);
    k_splitW1T<<<(1024 * 192 + 255) / 256, 256>>>(W1);

    // init MLP
    k_prep<<<(int)(((size_t)NR * 192 + 255) / 256), 256>>>(z_q, f_pr);
    k_mma64<192, 2><<<dim3(16, NR / 128), 256, MMA64_SMEM>>>(cHiP, w1HiP, w1LoP, b1);
    k_lngelu<<<NR, 256>>>(g1, be1);
    k_mma64<1024, 1><<<dim3(8, NR / 128), 256, MMA64_SMEM>>>(uHiP, w2HiP, w2LoP, b2);
    k_setx<<<NR / 256, 256>>>(start);

    // recurrence
    for (int t = 0; t < 20; ++t) {
        k_gru_mma<<<dim3(8, NR / 128), 512, GRU_SMEM>>>(W_ih, b_ih, b_hh, t);
        k_outhead<<<NR / 128, 512, OH_SMEM>>>(bo1, go, beo, Wo2, bo2, out, t);
    }
}